// round 1
// baseline (speedup 1.0000x reference)
#include <cuda_runtime.h>
#include <cuda_bf16.h>
#include <math.h>

// Problem constants: B=1, E=128, L=256, D=768, H=12, DH=64
#define EE 128
#define LL 256
#define DD 768
#define D3 2304
#define NROWS 32768          // E*L
#define NEGV (-10000.0f)

typedef unsigned long long ull;

// ------------------------- scratch (static device globals; no runtime alloc) -------------------------
__device__ float g_qkv[(size_t)NROWS * D3];   // 302 MB
__device__ float g_tmp[(size_t)NROWS * DD];   // 100 MB
__device__ float g_neg[NROWS];

// ------------------------- f32x2 packed-FMA helpers -------------------------
__device__ __forceinline__ ull f2pack(float x, float y) {
    ull r; asm("mov.b64 %0, {%1, %2};" : "=l"(r) : "f"(x), "f"(y)); return r;
}
__device__ __forceinline__ void f2unpack(ull v, float& x, float& y) {
    asm("mov.b64 {%0, %1}, %2;" : "=f"(x), "=f"(y) : "l"(v));
}
__device__ __forceinline__ ull ffma2(ull a, ull b, ull c) {
    ull d; asm("fma.rn.f32x2 %0, %1, %2, %3;" : "=l"(d) : "l"(a), "l"(b), "l"(c)); return d;
}

// ------------------------- padding mask -> additive neg, with dtype auto-detect -------------------------
__global__ void neg_kernel(const void* mraw) {
    __shared__ int notInt, notFloat;
    int tid = threadIdx.x;
    if (tid == 0) { notInt = 0; notFloat = 0; }
    __syncthreads();
    // Inspect first 8192 32-bit words (= 32768 bytes, safe for every candidate layout).
    const unsigned int* w = (const unsigned int*)mraw;
    int badI = 0, badF = 0;
    for (int i = tid; i < 8192; i += 256) {
        unsigned int v = w[i];
        if (v > 1u) badI = 1;
        if (v != 0u && v != 0x3F800000u) badF = 1;
    }
    if (badI) notInt = 1;
    if (badF) notFloat = 1;
    __syncthreads();
    int mode = (!notInt) ? 0 : ((!notFloat) ? 1 : 2);  // 0=int32, 1=float32, 2=uint8
    for (int i = tid; i < NROWS; i += 256) {
        bool m;
        if (mode == 0)      m = ((const int*)mraw)[i] != 0;
        else if (mode == 1) m = ((const float*)mraw)[i] != 0.0f;
        else                m = ((const unsigned char*)mraw)[i] != 0;
        g_neg[i] = m ? NEGV : 0.0f;
    }
}

// ------------------------- GEMM: C[M,N] = A[M,K] @ W[N,K]^T + bias[N] -------------------------
// BM=BN=128, BK=16, 256 threads, 8x8 per thread, f32x2 packed accumulation,
// register-stage double buffering of global loads.
__global__ __launch_bounds__(256, 2)
void gemm_bias_kernel(const float* __restrict__ A, const float* __restrict__ W,
                      const float* __restrict__ bias, float* __restrict__ C,
                      int M, int N, int K) {
    __shared__ float As[16][128];
    __shared__ float Bs[16][128];
    int tid = threadIdx.x;
    int tx = tid & 15, ty = tid >> 4;
    int bx = blockIdx.x, by = blockIdx.y;
    const float* Ab = A + (size_t)by * 128 * K;
    const float* Wb = W + (size_t)bx * 128 * K;

    ull acc[8][4];
#pragma unroll
    for (int i = 0; i < 8; i++)
#pragma unroll
        for (int p = 0; p < 4; p++) acc[i][p] = 0ull;

    int nk = K >> 4;
    // prefetch registers for tile kt
    float4 pa[2], pb[2];
    int rowp[2], kqp[2];
#pragma unroll
    for (int p = 0; p < 2; p++) {
        int f4 = tid + p * 256;
        rowp[p] = f4 >> 2; kqp[p] = (f4 & 3) << 2;
        pa[p] = *(const float4*)(Ab + (size_t)rowp[p] * K + kqp[p]);
        pb[p] = *(const float4*)(Wb + (size_t)rowp[p] * K + kqp[p]);
    }

    for (int kt = 0; kt < nk; ++kt) {
#pragma unroll
        for (int p = 0; p < 2; p++) {
            int row = rowp[p], kq = kqp[p];
            As[kq + 0][row] = pa[p].x; As[kq + 1][row] = pa[p].y;
            As[kq + 2][row] = pa[p].z; As[kq + 3][row] = pa[p].w;
            Bs[kq + 0][row] = pb[p].x; Bs[kq + 1][row] = pb[p].y;
            Bs[kq + 2][row] = pb[p].z; Bs[kq + 3][row] = pb[p].w;
        }
        __syncthreads();
        if (kt + 1 < nk) {
            int k0 = (kt + 1) * 16;
#pragma unroll
            for (int p = 0; p < 2; p++) {
                pa[p] = *(const float4*)(Ab + (size_t)rowp[p] * K + k0 + kqp[p]);
                pb[p] = *(const float4*)(Wb + (size_t)rowp[p] * K + k0 + kqp[p]);
            }
        }
#pragma unroll
        for (int kk = 0; kk < 16; kk++) {
            float4 af0 = *(const float4*)&As[kk][ty * 8];
            float4 af1 = *(const float4*)&As[kk][ty * 8 + 4];
            float4 bf0 = *(const float4*)&Bs[kk][tx * 8];
            float4 bf1 = *(const float4*)&Bs[kk][tx * 8 + 4];
            ull b2[4] = { f2pack(bf0.x, bf0.y), f2pack(bf0.z, bf0.w),
                          f2pack(bf1.x, bf1.y), f2pack(bf1.z, bf1.w) };
            float av[8] = { af0.x, af0.y, af0.z, af0.w, af1.x, af1.y, af1.z, af1.w };
#pragma unroll
            for (int i = 0; i < 8; i++) {
                ull a2 = f2pack(av[i], av[i]);
#pragma unroll
                for (int p = 0; p < 4; p++) acc[i][p] = ffma2(a2, b2[p], acc[i][p]);
            }
        }
        __syncthreads();
    }

    int n0 = bx * 128 + tx * 8;
    float bb[8];
#pragma unroll
    for (int u = 0; u < 8; u++) bb[u] = bias[n0 + u];
#pragma unroll
    for (int i = 0; i < 8; i++) {
        float o[8];
#pragma unroll
        for (int p = 0; p < 4; p++) f2unpack(acc[i][p], o[2 * p], o[2 * p + 1]);
#pragma unroll
        for (int u = 0; u < 8; u++) o[u] += bb[u];
        float* Cp = C + (size_t)(by * 128 + ty * 8 + i) * N + n0;
        *(float4*)Cp       = make_float4(o[0], o[1], o[2], o[3]);
        *(float4*)(Cp + 4) = make_float4(o[4], o[5], o[6], o[7]);
    }
}

// ------------------------- fused attention (one (group, head, i-tile of 64) per block) -------------------------
// Works for row attention (group=e, seq over L=256) and col attention (group=l, seq over E=128).
template<int S>
__global__ __launch_bounds__(256)
void attn_kernel(const float* __restrict__ qkv,
                 long groupStride, long posStride,
                 const float* __restrict__ neg, long negGroupStride, long negStride,
                 float* __restrict__ outp, long outGroupStride, long outPosStride) {
    constexpr int JPT = S / 32;
    extern __shared__ float sm[];
    float* Ks   = sm;                    // S x 65 (padded)
    float* Vs   = Ks + S * 65;           // S x 65
    float* Qs   = Vs + S * 65;           // 64 x 65
    float* negs = Qs + 64 * 65;          // S
    float* Ps   = Ks;                    // alias K region after scores done; stride S+1

    int h   = blockIdx.y;
    int grp = blockIdx.z;
    int i0  = blockIdx.x * 64;
    const float* base = qkv + (size_t)grp * groupStride;
    const float* qb = base + h * 64;
    const float* kb = base + 768 + h * 64;
    const float* vb = base + 1536 + h * 64;
    int tid = threadIdx.x;

    // load K, V tiles
    for (int idx = tid; idx < S * 16; idx += 256) {
        int j = idx >> 4, c4 = (idx & 15) << 2;
        float4 k4 = *(const float4*)(kb + (size_t)j * posStride + c4);
        float4 v4 = *(const float4*)(vb + (size_t)j * posStride + c4);
        float* kd = &Ks[j * 65 + c4];
        kd[0] = k4.x; kd[1] = k4.y; kd[2] = k4.z; kd[3] = k4.w;
        float* vd = &Vs[j * 65 + c4];
        vd[0] = v4.x; vd[1] = v4.y; vd[2] = v4.z; vd[3] = v4.w;
    }
    // load Q tile (pre-scaled by DH^-0.5 = 0.125)
    for (int idx = tid; idx < 64 * 16; idx += 256) {
        int i = idx >> 4, c4 = (idx & 15) << 2;
        float4 q4 = *(const float4*)(qb + (size_t)(i0 + i) * posStride + c4);
        float* qd = &Qs[i * 65 + c4];
        qd[0] = q4.x * 0.125f; qd[1] = q4.y * 0.125f;
        qd[2] = q4.z * 0.125f; qd[3] = q4.w * 0.125f;
    }
    if (tid < S) negs[tid] = neg[(size_t)grp * negGroupStride + (size_t)tid * negStride];
    __syncthreads();

    int ty = tid >> 5, lane = tid & 31;

    // ---- scores: S_reg[ii][jj] for rows i0+ty*8+ii, cols j = jj*32+lane ----
    float sreg[8][JPT];
#pragma unroll
    for (int ii = 0; ii < 8; ii++)
#pragma unroll
        for (int jj = 0; jj < JPT; jj++) sreg[ii][jj] = 0.0f;

#pragma unroll 4
    for (int kk = 0; kk < 64; kk++) {
        float a[8];
#pragma unroll
        for (int ii = 0; ii < 8; ii++) a[ii] = Qs[(ty * 8 + ii) * 65 + kk];
#pragma unroll
        for (int jj = 0; jj < JPT; jj++) {
            float kv = Ks[(jj * 32 + lane) * 65 + kk];
#pragma unroll
            for (int ii = 0; ii < 8; ii++) sreg[ii][jj] += a[ii] * kv;
        }
    }

    // ---- mask + softmax (rows live across the warp's lanes) ----
#pragma unroll
    for (int ii = 0; ii < 8; ii++) {
        float mx = -3.4e38f;
#pragma unroll
        for (int jj = 0; jj < JPT; jj++) {
            sreg[ii][jj] += negs[jj * 32 + lane];
            mx = fmaxf(mx, sreg[ii][jj]);
        }
#pragma unroll
        for (int o = 16; o > 0; o >>= 1) mx = fmaxf(mx, __shfl_xor_sync(0xffffffffu, mx, o));
        float sum = 0.0f;
#pragma unroll
        for (int jj = 0; jj < JPT; jj++) {
            float p = __expf(sreg[ii][jj] - mx);
            sreg[ii][jj] = p; sum += p;
        }
#pragma unroll
        for (int o = 16; o > 0; o >>= 1) sum += __shfl_xor_sync(0xffffffffu, sum, o);
        float inv = 1.0f / sum;
#pragma unroll
        for (int jj = 0; jj < JPT; jj++) sreg[ii][jj] *= inv;
    }

    __syncthreads();   // all warps done reading Ks before P overwrites it
#pragma unroll
    for (int ii = 0; ii < 8; ii++)
#pragma unroll
        for (int jj = 0; jj < JPT; jj++)
            Ps[(ty * 8 + ii) * (S + 1) + jj * 32 + lane] = sreg[ii][jj];
    __syncthreads();

    // ---- O = P @ V : each lane owns cols d=lane and d=lane+32 ----
    float o0[8], o1[8];
#pragma unroll
    for (int ii = 0; ii < 8; ii++) { o0[ii] = 0.0f; o1[ii] = 0.0f; }
#pragma unroll 4
    for (int j = 0; j < S; j++) {
        float v0 = Vs[j * 65 + lane];
        float v1 = Vs[j * 65 + lane + 32];
#pragma unroll
        for (int ii = 0; ii < 8; ii++) {
            float p = Ps[(ty * 8 + ii) * (S + 1) + j];
            o0[ii] += p * v0; o1[ii] += p * v1;
        }
    }
#pragma unroll
    for (int ii = 0; ii < 8; ii++) {
        float* op = outp + (size_t)grp * outGroupStride
                         + (size_t)(i0 + ty * 8 + ii) * outPosStride + h * 64;
        op[lane]      = o0[ii];
        op[lane + 32] = o1[ii];
    }
}

// ------------------------- residual + LayerNorm (one row of 768 per block) -------------------------
__global__ __launch_bounds__(256)
void ln_kernel(const float* __restrict__ x, const float* __restrict__ r,
               const float* __restrict__ g, const float* __restrict__ b,
               float* __restrict__ out) {
    __shared__ float rs[8], rq[8], sh[2];
    int row = blockIdx.x, tid = threadIdx.x;
    size_t b0 = (size_t)row * DD;
    float v[3]; float s = 0.0f, q = 0.0f;
#pragma unroll
    for (int u = 0; u < 3; u++) {
        int c = tid + u * 256;
        float t = x[b0 + c] + r[b0 + c];
        v[u] = t; s += t; q += t * t;
    }
#pragma unroll
    for (int o = 16; o > 0; o >>= 1) {
        s += __shfl_down_sync(0xffffffffu, s, o);
        q += __shfl_down_sync(0xffffffffu, q, o);
    }
    int wid = tid >> 5, lane = tid & 31;
    if (lane == 0) { rs[wid] = s; rq[wid] = q; }
    __syncthreads();
    if (tid == 0) {
        float S = 0.0f, Q = 0.0f;
#pragma unroll
        for (int w = 0; w < 8; w++) { S += rs[w]; Q += rq[w]; }
        float mu = S * (1.0f / 768.0f);
        sh[0] = mu;
        sh[1] = rsqrtf(Q * (1.0f / 768.0f) - mu * mu + 1e-5f);
    }
    __syncthreads();
    float mu = sh[0], inv = sh[1];
#pragma unroll
    for (int u = 0; u < 3; u++) {
        int c = tid + u * 256;
        out[b0 + c] = (v[u] - mu) * inv * g[c] + b[c];
    }
}

// ------------------------- launch -------------------------
extern "C" void kernel_launch(void* const* d_in, const int* in_sizes, int n_in,
                              void* d_out, int out_size) {
    const float* x     = (const float*)d_in[0];
    const float* w_row = (const float*)d_in[1];
    const float* b_row = (const float*)d_in[2];
    const float* w_col = (const float*)d_in[3];
    const float* b_col = (const float*)d_in[4];
    const float* g1    = (const float*)d_in[5];
    const float* be1   = (const float*)d_in[6];
    const float* g2    = (const float*)d_in[7];
    const float* be2   = (const float*)d_in[8];
    const void*  mask  = d_in[9];
    float* out = (float*)d_out;

    float *qkv, *tmp, *neg;
    cudaGetSymbolAddress((void**)&qkv, g_qkv);
    cudaGetSymbolAddress((void**)&tmp, g_tmp);
    cudaGetSymbolAddress((void**)&neg, g_neg);

    const int SMEM_ROW = (2 * 256 * 65 + 64 * 65 + 256) * 4;   // 150784 B
    const int SMEM_COL = (2 * 128 * 65 + 64 * 65 + 128) * 4;   // 83712 B
    cudaFuncSetAttribute(attn_kernel<256>, cudaFuncAttributeMaxDynamicSharedMemorySize, SMEM_ROW);
    cudaFuncSetAttribute(attn_kernel<128>, cudaFuncAttributeMaxDynamicSharedMemorySize, SMEM_COL);

    neg_kernel<<<1, 256>>>(mask);

    dim3 ggrid(D3 / 128, NROWS / 128);

    // ---- row attention block ----
    gemm_bias_kernel<<<ggrid, 256>>>(x, w_row, b_row, qkv, NROWS, D3, DD);
    {
        dim3 agrid(LL / 64, 12, EE);  // (i-tile, head, e-group)
        attn_kernel<256><<<agrid, 256, SMEM_ROW>>>(
            qkv, (long)LL * D3, (long)D3,
            neg, (long)LL, 1L,
            tmp, (long)LL * DD, (long)DD);
    }
    ln_kernel<<<NROWS, 256>>>(x, tmp, g1, be1, out);

    // ---- column attention block ----
    gemm_bias_kernel<<<ggrid, 256>>>(out, w_col, b_col, qkv, NROWS, D3, DD);
    {
        dim3 agrid(EE / 64, 12, LL);  // (i-tile, head, l-group)
        attn_kernel<128><<<agrid, 256, SMEM_COL>>>(
            qkv, (long)D3, (long)LL * D3,
            neg, 1L, (long)LL,
            tmp, (long)DD, (long)LL * DD);
    }
    ln_kernel<<<NROWS, 256>>>(out, tmp, g2, be2, out);
}

// round 4
// speedup vs baseline: 2.0270x; 2.0270x over previous
#include <cuda_runtime.h>
#include <cuda_bf16.h>
#include <stdint.h>
#include <math.h>

// Problem constants: B=1, E=128, L=256, D=768, H=12, DH=64
#define EE 128
#define LL 256
#define DD 768
#define D3 2304
#define NROWS 32768          // E*L
#define NEGV (-10000.0f)

typedef unsigned long long ull;

// ------------------------- scratch (static device globals; no runtime alloc) -------------------------
__device__ float g_qkv[(size_t)NROWS * D3];   // 302 MB
__device__ float g_tmp[(size_t)NROWS * DD];   // 100 MB
__device__ float g_neg[NROWS];

// ------------------------- PTX helpers -------------------------
__device__ __forceinline__ uint32_t smem_u32(const void* p) {
    uint32_t a;
    asm("{ .reg .u64 t; cvta.to.shared.u64 t, %1; cvt.u32.u64 %0, t; }" : "=r"(a) : "l"(p));
    return a;
}
__device__ __forceinline__ void cp_async16(uint32_t dst, const void* src) {
    asm volatile("cp.async.cg.shared.global [%0], [%1], 16;" :: "r"(dst), "l"(src) : "memory");
}
__device__ __forceinline__ uint32_t f2tf(float f) {
    uint32_t r; asm("cvt.rna.tf32.f32 %0, %1;" : "=r"(r) : "f"(f)); return r;
}
__device__ __forceinline__ void mma8(float* c, uint32_t a0, uint32_t a1, uint32_t a2, uint32_t a3,
                                     uint32_t b0, uint32_t b1) {
    asm volatile(
        "mma.sync.aligned.m16n8k8.row.col.f32.tf32.tf32.f32 "
        "{%0,%1,%2,%3}, {%4,%5,%6,%7}, {%8,%9}, {%0,%1,%2,%3};"
        : "+f"(c[0]), "+f"(c[1]), "+f"(c[2]), "+f"(c[3])
        : "r"(a0), "r"(a1), "r"(a2), "r"(a3), "r"(b0), "r"(b1));
}

// ------------------------- padding mask -> additive neg, with dtype auto-detect -------------------------
__global__ void neg_kernel(const void* mraw) {
    __shared__ int notInt, notFloat;
    int tid = threadIdx.x;
    if (tid == 0) { notInt = 0; notFloat = 0; }
    __syncthreads();
    const unsigned int* w = (const unsigned int*)mraw;
    int badI = 0, badF = 0;
    for (int i = tid; i < 8192; i += 256) {
        unsigned int v = w[i];
        if (v > 1u) badI = 1;
        if (v != 0u && v != 0x3F800000u) badF = 1;
    }
    if (badI) notInt = 1;
    if (badF) notFloat = 1;
    __syncthreads();
    int mode = (!notInt) ? 0 : ((!notFloat) ? 1 : 2);  // 0=int32, 1=float32, 2=uint8
    for (int i = tid; i < NROWS; i += 256) {
        bool m;
        if (mode == 0)      m = ((const int*)mraw)[i] != 0;
        else if (mode == 1) m = ((const float*)mraw)[i] != 0.0f;
        else                m = ((const unsigned char*)mraw)[i] != 0;
        g_neg[i] = m ? NEGV : 0.0f;
    }
}

// ------------------------- tf32 mma.sync GEMM: C[M,2304] = A[M,768] @ W[2304,768]^T + bias -------------------------
// CTA tile M=128 x N=256, 8 warps (warp tile 64x64), K chunk 32, 3-stage cp.async pipeline.
// smem row stride 36 floats -> conflict-free m16n8k8 fragment loads (bank == lane).
#define GM 128
#define GN 256
#define KB 32
#define NST 24                       // 768/32
#define ASTR 36
#define AFLOATS (128 * ASTR)         // 4608
#define BFLOATS (256 * ASTR)         // 9216
#define STAGEF (AFLOATS + BFLOATS)   // 13824 floats
#define GEMM_SMEM (3 * STAGEF * 4)   // 165888 bytes

__device__ __forceinline__ void load_stage(float* sm, int stg, const float* Ab, const float* Wb,
                                           int k0, int tid) {
    float* As = sm + stg * STAGEF;
    float* Bs = As + AFLOATS;
    uint32_t as_u = smem_u32(As), bs_u = smem_u32(Bs);
#pragma unroll
    for (int i = 0; i < 4; i++) {            // A: 128 rows x 8 chunks of 16B
        int idx = tid + i * 256;
        int row = idx >> 3, ch = idx & 7;
        cp_async16(as_u + row * (ASTR * 4) + ch * 16, Ab + (size_t)row * DD + k0 + ch * 4);
    }
#pragma unroll
    for (int i = 0; i < 8; i++) {            // B: 256 rows x 8 chunks of 16B
        int idx = tid + i * 256;
        int row = idx >> 3, ch = idx & 7;
        cp_async16(bs_u + row * (ASTR * 4) + ch * 16, Wb + (size_t)row * DD + k0 + ch * 4);
    }
}

__global__ __launch_bounds__(256, 1)
void gemm_mma_kernel(const float* __restrict__ A, const float* __restrict__ W,
                     const float* __restrict__ bias, float* __restrict__ C) {
    extern __shared__ float sm[];
    int tid = threadIdx.x, lane = tid & 31, w = tid >> 5;
    int wm = w & 1, wn = w >> 1;              // warp grid 2 (m) x 4 (n)
    int m0 = blockIdx.y * GM, n0 = blockIdx.x * GN;
    const float* Ab = A + (size_t)m0 * DD;
    const float* Wb = W + (size_t)n0 * DD;
    int r0 = lane >> 2, c0 = lane & 3;

    float acc[4][8][4];
#pragma unroll
    for (int mt = 0; mt < 4; mt++)
#pragma unroll
        for (int nt = 0; nt < 8; nt++)
#pragma unroll
            for (int q = 0; q < 4; q++) acc[mt][nt][q] = 0.0f;

    load_stage(sm, 0, Ab, Wb, 0, tid);
    asm volatile("cp.async.commit_group;" ::: "memory");
    load_stage(sm, 1, Ab, Wb, KB, tid);
    asm volatile("cp.async.commit_group;" ::: "memory");

    for (int s = 0; s < NST; ++s) {
        int b = s % 3;
        asm volatile("cp.async.wait_group 1;" ::: "memory");
        __syncthreads();
        if (s + 2 < NST) load_stage(sm, (s + 2) % 3, Ab, Wb, (s + 2) * KB, tid);
        asm volatile("cp.async.commit_group;" ::: "memory");

        float* As = sm + b * STAGEF;
        float* Bs = As + AFLOATS;
#pragma unroll
        for (int ks = 0; ks < 4; ks++) {
            int K0 = ks * 8 + c0;
            uint32_t bf[8][2];
#pragma unroll
            for (int nt = 0; nt < 8; nt++) {
                int N0 = wn * 64 + nt * 8 + r0;
                bf[nt][0] = f2tf(Bs[N0 * ASTR + K0]);
                bf[nt][1] = f2tf(Bs[N0 * ASTR + K0 + 4]);
            }
#pragma unroll
            for (int mt = 0; mt < 4; mt++) {
                int R = wm * 64 + mt * 16 + r0;
                uint32_t a0 = f2tf(As[R * ASTR + K0]);
                uint32_t a1 = f2tf(As[(R + 8) * ASTR + K0]);
                uint32_t a2 = f2tf(As[R * ASTR + K0 + 4]);
                uint32_t a3 = f2tf(As[(R + 8) * ASTR + K0 + 4]);
#pragma unroll
                for (int nt = 0; nt < 8; nt++)
                    mma8(acc[mt][nt], a0, a1, a2, a3, bf[nt][0], bf[nt][1]);
            }
        }
    }
    asm volatile("cp.async.wait_group 0;" ::: "memory");

    // epilogue: c frag rows = r0 / r0+8, cols = c0*2 / c0*2+1
#pragma unroll
    for (int nt = 0; nt < 8; nt++) {
        int col = n0 + wn * 64 + nt * 8 + c0 * 2;
        float b0v = bias[col], b1v = bias[col + 1];
#pragma unroll
        for (int mt = 0; mt < 4; mt++) {
            int row = m0 + wm * 64 + mt * 16 + r0;
            float2 v0 = make_float2(acc[mt][nt][0] + b0v, acc[mt][nt][1] + b1v);
            float2 v1 = make_float2(acc[mt][nt][2] + b0v, acc[mt][nt][3] + b1v);
            *(float2*)&C[(size_t)row * D3 + col] = v0;
            *(float2*)&C[(size_t)(row + 8) * D3 + col] = v1;
        }
    }
}

// ------------------------- fused attention (one (group, head, i-tile of 64) per block) -------------------------
template<int S>
__global__ __launch_bounds__(256)
void attn_kernel(const float* __restrict__ qkv,
                 long groupStride, long posStride,
                 const float* __restrict__ neg, long negGroupStride, long negStride,
                 float* __restrict__ outp, long outGroupStride, long outPosStride) {
    constexpr int JPT = S / 32;
    extern __shared__ float smf[];
    float* Ks   = smf;
    float* Vs   = Ks + S * 65;
    float* Qs   = Vs + S * 65;
    float* negs = Qs + 64 * 65;
    float* Ps   = Ks;   // alias after scores done; stride S+1

    int h   = blockIdx.y;
    int grp = blockIdx.z;
    int i0  = blockIdx.x * 64;
    const float* base = qkv + (size_t)grp * groupStride;
    const float* qb = base + h * 64;
    const float* kb = base + 768 + h * 64;
    const float* vb = base + 1536 + h * 64;
    int tid = threadIdx.x;

    for (int idx = tid; idx < S * 16; idx += 256) {
        int j = idx >> 4, c4 = (idx & 15) << 2;
        float4 k4 = *(const float4*)(kb + (size_t)j * posStride + c4);
        float4 v4 = *(const float4*)(vb + (size_t)j * posStride + c4);
        float* kd = &Ks[j * 65 + c4];
        kd[0] = k4.x; kd[1] = k4.y; kd[2] = k4.z; kd[3] = k4.w;
        float* vd = &Vs[j * 65 + c4];
        vd[0] = v4.x; vd[1] = v4.y; vd[2] = v4.z; vd[3] = v4.w;
    }
    for (int idx = tid; idx < 64 * 16; idx += 256) {
        int i = idx >> 4, c4 = (idx & 15) << 2;
        float4 q4 = *(const float4*)(qb + (size_t)(i0 + i) * posStride + c4);
        float* qd = &Qs[i * 65 + c4];
        qd[0] = q4.x * 0.125f; qd[1] = q4.y * 0.125f;
        qd[2] = q4.z * 0.125f; qd[3] = q4.w * 0.125f;
    }
    if (tid < S) negs[tid] = neg[(size_t)grp * negGroupStride + (size_t)tid * negStride];
    __syncthreads();

    int ty = tid >> 5, lane = tid & 31;

    float sreg[8][JPT];
#pragma unroll
    for (int ii = 0; ii < 8; ii++)
#pragma unroll
        for (int jj = 0; jj < JPT; jj++) sreg[ii][jj] = 0.0f;

#pragma unroll 4
    for (int kk = 0; kk < 64; kk++) {
        float a[8];
#pragma unroll
        for (int ii = 0; ii < 8; ii++) a[ii] = Qs[(ty * 8 + ii) * 65 + kk];
#pragma unroll
        for (int jj = 0; jj < JPT; jj++) {
            float kv = Ks[(jj * 32 + lane) * 65 + kk];
#pragma unroll
            for (int ii = 0; ii < 8; ii++) sreg[ii][jj] += a[ii] * kv;
        }
    }

#pragma unroll
    for (int ii = 0; ii < 8; ii++) {
        float mx = -3.4e38f;
#pragma unroll
        for (int jj = 0; jj < JPT; jj++) {
            sreg[ii][jj] += negs[jj * 32 + lane];
            mx = fmaxf(mx, sreg[ii][jj]);
        }
#pragma unroll
        for (int o = 16; o > 0; o >>= 1) mx = fmaxf(mx, __shfl_xor_sync(0xffffffffu, mx, o));
        float sum = 0.0f;
#pragma unroll
        for (int jj = 0; jj < JPT; jj++) {
            float p = __expf(sreg[ii][jj] - mx);
            sreg[ii][jj] = p; sum += p;
        }
#pragma unroll
        for (int o = 16; o > 0; o >>= 1) sum += __shfl_xor_sync(0xffffffffu, sum, o);
        float inv = 1.0f / sum;
#pragma unroll
        for (int jj = 0; jj < JPT; jj++) sreg[ii][jj] *= inv;
    }

    __syncthreads();
#pragma unroll
    for (int ii = 0; ii < 8; ii++)
#pragma unroll
        for (int jj = 0; jj < JPT; jj++)
            Ps[(ty * 8 + ii) * (S + 1) + jj * 32 + lane] = sreg[ii][jj];
    __syncthreads();

    float o0[8], o1[8];
#pragma unroll
    for (int ii = 0; ii < 8; ii++) { o0[ii] = 0.0f; o1[ii] = 0.0f; }
#pragma unroll 4
    for (int j = 0; j < S; j++) {
        float v0 = Vs[j * 65 + lane];
        float v1 = Vs[j * 65 + lane + 32];
#pragma unroll
        for (int ii = 0; ii < 8; ii++) {
            float p = Ps[(ty * 8 + ii) * (S + 1) + j];
            o0[ii] += p * v0; o1[ii] += p * v1;
        }
    }
#pragma unroll
    for (int ii = 0; ii < 8; ii++) {
        float* op = outp + (size_t)grp * outGroupStride
                         + (size_t)(i0 + ty * 8 + ii) * outPosStride + h * 64;
        op[lane]      = o0[ii];
        op[lane + 32] = o1[ii];
    }
}

// ------------------------- residual + LayerNorm -------------------------
__global__ __launch_bounds__(256)
void ln_kernel(const float* __restrict__ x, const float* __restrict__ r,
               const float* __restrict__ g, const float* __restrict__ b,
               float* __restrict__ out) {
    __shared__ float rs[8], rq[8], sh[2];
    int row = blockIdx.x, tid = threadIdx.x;
    size_t b0 = (size_t)row * DD;
    float v[3]; float s = 0.0f, q = 0.0f;
#pragma unroll
    for (int u = 0; u < 3; u++) {
        int c = tid + u * 256;
        float t = x[b0 + c] + r[b0 + c];
        v[u] = t; s += t; q += t * t;
    }
#pragma unroll
    for (int o = 16; o > 0; o >>= 1) {
        s += __shfl_down_sync(0xffffffffu, s, o);
        q += __shfl_down_sync(0xffffffffu, q, o);
    }
    int wid = tid >> 5, lane = tid & 31;
    if (lane == 0) { rs[wid] = s; rq[wid] = q; }
    __syncthreads();
    if (tid == 0) {
        float S = 0.0f, Q = 0.0f;
#pragma unroll
        for (int w = 0; w < 8; w++) { S += rs[w]; Q += rq[w]; }
        float mu = S * (1.0f / 768.0f);
        sh[0] = mu;
        sh[1] = rsqrtf(Q * (1.0f / 768.0f) - mu * mu + 1e-5f);
    }
    __syncthreads();
    float mu = sh[0], inv = sh[1];
#pragma unroll
    for (int u = 0; u < 3; u++) {
        int c = tid + u * 256;
        out[b0 + c] = (v[u] - mu) * inv * g[c] + b[c];
    }
}

// ------------------------- launch -------------------------
extern "C" void kernel_launch(void* const* d_in, const int* in_sizes, int n_in,
                              void* d_out, int out_size) {
    const float* x     = (const float*)d_in[0];
    const float* w_row = (const float*)d_in[1];
    const float* b_row = (const float*)d_in[2];
    const float* w_col = (const float*)d_in[3];
    const float* b_col = (const float*)d_in[4];
    const float* g1    = (const float*)d_in[5];
    const float* be1   = (const float*)d_in[6];
    const float* g2    = (const float*)d_in[7];
    const float* be2   = (const float*)d_in[8];
    const void*  mask  = d_in[9];
    float* out = (float*)d_out;

    float *qkv, *tmp, *neg;
    cudaGetSymbolAddress((void**)&qkv, g_qkv);
    cudaGetSymbolAddress((void**)&tmp, g_tmp);
    cudaGetSymbolAddress((void**)&neg, g_neg);

    const int SMEM_ROW = (2 * 256 * 65 + 64 * 65 + 256) * 4;
    const int SMEM_COL = (2 * 128 * 65 + 64 * 65 + 128) * 4;
    cudaFuncSetAttribute(attn_kernel<256>, cudaFuncAttributeMaxDynamicSharedMemorySize, SMEM_ROW);
    cudaFuncSetAttribute(attn_kernel<128>, cudaFuncAttributeMaxDynamicSharedMemorySize, SMEM_COL);
    cudaFuncSetAttribute(gemm_mma_kernel, cudaFuncAttributeMaxDynamicSharedMemorySize, GEMM_SMEM);

    neg_kernel<<<1, 256>>>(mask);

    dim3 ggrid(D3 / GN, NROWS / GM);   // (9, 256)

    // ---- row attention block ----
    gemm_mma_kernel<<<ggrid, 256, GEMM_SMEM>>>(x, w_row, b_row, qkv);
    {
        dim3 agrid(LL / 64, 12, EE);
        attn_kernel<256><<<agrid, 256, SMEM_ROW>>>(
            qkv, (long)LL * D3, (long)D3,
            neg, (long)LL, 1L,
            tmp, (long)LL * DD, (long)DD);
    }
    ln_kernel<<<NROWS, 256>>>(x, tmp, g1, be1, out);

    // ---- column attention block ----
    gemm_mma_kernel<<<ggrid, 256, GEMM_SMEM>>>(out, w_col, b_col, qkv);
    {
        dim3 agrid(EE / 64, 12, LL);
        attn_kernel<128><<<agrid, 256, SMEM_COL>>>(
            qkv, (long)D3, (long)LL * D3,
            neg, 1L, (long)LL,
            tmp, (long)DD, (long)LL * DD);
    }
    ln_kernel<<<NROWS, 256>>>(out, tmp, g2, be2, out);
}

// round 5
// speedup vs baseline: 2.3679x; 1.1682x over previous
#include <cuda_runtime.h>
#include <cuda_bf16.h>
#include <stdint.h>
#include <math.h>

// Problem constants: B=1, E=128, L=256, D=768, H=12, DH=64
#define EE 128
#define LL 256
#define DD 768
#define D3 2304
#define NROWS 32768          // E*L
#define NEGV (-10000.0f)

typedef unsigned long long ull;

// ------------------------- scratch (static device globals; no runtime alloc) -------------------------
__device__ float g_qkv[(size_t)NROWS * D3];   // 302 MB
__device__ float g_tmp[(size_t)NROWS * DD];   // 100 MB
__device__ float g_neg[NROWS];

// ------------------------- PTX helpers -------------------------
__device__ __forceinline__ uint32_t smem_u32(const void* p) {
    uint32_t a;
    asm("{ .reg .u64 t; cvta.to.shared.u64 t, %1; cvt.u32.u64 %0, t; }" : "=r"(a) : "l"(p));
    return a;
}
__device__ __forceinline__ void cp_async16(uint32_t dst, const void* src) {
    asm volatile("cp.async.cg.shared.global [%0], [%1], 16;" :: "r"(dst), "l"(src) : "memory");
}
__device__ __forceinline__ uint32_t f2tf(float f) {
    uint32_t r; asm("cvt.rna.tf32.f32 %0, %1;" : "=r"(r) : "f"(f)); return r;
}
__device__ __forceinline__ void mma8(float* c, uint32_t a0, uint32_t a1, uint32_t a2, uint32_t a3,
                                     uint32_t b0, uint32_t b1) {
    asm volatile(
        "mma.sync.aligned.m16n8k8.row.col.f32.tf32.tf32.f32 "
        "{%0,%1,%2,%3}, {%4,%5,%6,%7}, {%8,%9}, {%0,%1,%2,%3};"
        : "+f"(c[0]), "+f"(c[1]), "+f"(c[2]), "+f"(c[3])
        : "r"(a0), "r"(a1), "r"(a2), "r"(a3), "r"(b0), "r"(b1));
}

// ------------------------- padding mask -> additive neg, with dtype auto-detect -------------------------
__global__ void neg_kernel(const void* mraw) {
    __shared__ int notInt, notFloat;
    int tid = threadIdx.x;
    if (tid == 0) { notInt = 0; notFloat = 0; }
    __syncthreads();
    const unsigned int* w = (const unsigned int*)mraw;
    int badI = 0, badF = 0;
    for (int i = tid; i < 8192; i += 256) {
        unsigned int v = w[i];
        if (v > 1u) badI = 1;
        if (v != 0u && v != 0x3F800000u) badF = 1;
    }
    if (badI) notInt = 1;
    if (badF) notFloat = 1;
    __syncthreads();
    int mode = (!notInt) ? 0 : ((!notFloat) ? 1 : 2);  // 0=int32, 1=float32, 2=uint8
    for (int i = tid; i < NROWS; i += 256) {
        bool m;
        if (mode == 0)      m = ((const int*)mraw)[i] != 0;
        else if (mode == 1) m = ((const float*)mraw)[i] != 0.0f;
        else                m = ((const unsigned char*)mraw)[i] != 0;
        g_neg[i] = m ? NEGV : 0.0f;
    }
}

// ------------------------- tf32 mma.sync GEMM: C[M,2304] = A[M,768] @ W[2304,768]^T + bias -------------------------
#define GM 128
#define GN 256
#define KB 32
#define NST 24                       // 768/32
#define ASTR 36
#define AFLOATS (128 * ASTR)         // 4608
#define BFLOATS (256 * ASTR)         // 9216
#define STAGEF (AFLOATS + BFLOATS)   // 13824 floats
#define GEMM_SMEM (3 * STAGEF * 4)   // 165888 bytes

__device__ __forceinline__ void load_stage(float* sm, int stg, const float* Ab, const float* Wb,
                                           int k0, int tid) {
    float* As = sm + stg * STAGEF;
    float* Bs = As + AFLOATS;
    uint32_t as_u = smem_u32(As), bs_u = smem_u32(Bs);
#pragma unroll
    for (int i = 0; i < 4; i++) {
        int idx = tid + i * 256;
        int row = idx >> 3, ch = idx & 7;
        cp_async16(as_u + row * (ASTR * 4) + ch * 16, Ab + (size_t)row * DD + k0 + ch * 4);
    }
#pragma unroll
    for (int i = 0; i < 8; i++) {
        int idx = tid + i * 256;
        int row = idx >> 3, ch = idx & 7;
        cp_async16(bs_u + row * (ASTR * 4) + ch * 16, Wb + (size_t)row * DD + k0 + ch * 4);
    }
}

__global__ __launch_bounds__(256, 1)
void gemm_mma_kernel(const float* __restrict__ A, const float* __restrict__ W,
                     const float* __restrict__ bias, float* __restrict__ C) {
    extern __shared__ float sm[];
    int tid = threadIdx.x, lane = tid & 31, w = tid >> 5;
    int wm = w & 1, wn = w >> 1;
    int m0 = blockIdx.y * GM, n0 = blockIdx.x * GN;
    const float* Ab = A + (size_t)m0 * DD;
    const float* Wb = W + (size_t)n0 * DD;
    int r0 = lane >> 2, c0 = lane & 3;

    float acc[4][8][4];
#pragma unroll
    for (int mt = 0; mt < 4; mt++)
#pragma unroll
        for (int nt = 0; nt < 8; nt++)
#pragma unroll
            for (int q = 0; q < 4; q++) acc[mt][nt][q] = 0.0f;

    load_stage(sm, 0, Ab, Wb, 0, tid);
    asm volatile("cp.async.commit_group;" ::: "memory");
    load_stage(sm, 1, Ab, Wb, KB, tid);
    asm volatile("cp.async.commit_group;" ::: "memory");

    for (int s = 0; s < NST; ++s) {
        int b = s % 3;
        asm volatile("cp.async.wait_group 1;" ::: "memory");
        __syncthreads();
        if (s + 2 < NST) load_stage(sm, (s + 2) % 3, Ab, Wb, (s + 2) * KB, tid);
        asm volatile("cp.async.commit_group;" ::: "memory");

        float* As = sm + b * STAGEF;
        float* Bs = As + AFLOATS;
#pragma unroll
        for (int ks = 0; ks < 4; ks++) {
            int K0 = ks * 8 + c0;
            uint32_t bf[8][2];
#pragma unroll
            for (int nt = 0; nt < 8; nt++) {
                int N0 = wn * 64 + nt * 8 + r0;
                bf[nt][0] = f2tf(Bs[N0 * ASTR + K0]);
                bf[nt][1] = f2tf(Bs[N0 * ASTR + K0 + 4]);
            }
#pragma unroll
            for (int mt = 0; mt < 4; mt++) {
                int R = wm * 64 + mt * 16 + r0;
                uint32_t a0 = f2tf(As[R * ASTR + K0]);
                uint32_t a1 = f2tf(As[(R + 8) * ASTR + K0]);
                uint32_t a2 = f2tf(As[R * ASTR + K0 + 4]);
                uint32_t a3 = f2tf(As[(R + 8) * ASTR + K0 + 4]);
#pragma unroll
                for (int nt = 0; nt < 8; nt++)
                    mma8(acc[mt][nt], a0, a1, a2, a3, bf[nt][0], bf[nt][1]);
            }
        }
    }
    asm volatile("cp.async.wait_group 0;" ::: "memory");

#pragma unroll
    for (int nt = 0; nt < 8; nt++) {
        int col = n0 + wn * 64 + nt * 8 + c0 * 2;
        float b0v = bias[col], b1v = bias[col + 1];
#pragma unroll
        for (int mt = 0; mt < 4; mt++) {
            int row = m0 + wm * 64 + mt * 16 + r0;
            float2 v0 = make_float2(acc[mt][nt][0] + b0v, acc[mt][nt][1] + b1v);
            float2 v1 = make_float2(acc[mt][nt][2] + b0v, acc[mt][nt][3] + b1v);
            *(float2*)&C[(size_t)row * D3 + col] = v0;
            *(float2*)&C[(size_t)(row + 8) * D3 + col] = v1;
        }
    }
}

// ------------------------- tensor-core attention -------------------------
// Block: 64 query rows x one head x one group. 8 warps.
// QK phase: warp = (row-quarter wr = w&3, key-half sh = w>>2); 16x(S/2) scores each.
// Softmax: in-register on C-fragment layout; cross-half stats via smem; P (unnormalized
// exp) written to smem aliasing Ks; output scaled by 1/sum at store.
// PV phase: warp = (row-quarter, dim-half); A=P from smem, B=V^T from smem.
#define QSTR 68
#define KSTR 68
#define VSTR 72
#define PSTR 260

template<int S>
__global__ __launch_bounds__(256)
void attn_tc_kernel(const float* __restrict__ qkv,
                    long groupStride, long posStride,
                    const float* __restrict__ neg, long negGroupStride, long negStride,
                    float* __restrict__ outp, long outGroupStride, long outPosStride) {
    constexpr int HS = S / 2;
    constexpr int NT = HS / 8;          // 16 (S=256) / 8 (S=128)
    extern __shared__ float smf[];
    float* Vs   = smf;                  // S x VSTR
    float* Qs   = Vs + S * VSTR;        // 64 x QSTR
    float* negs = Qs + 64 * QSTR;       // S
    float* pmax = negs + S;             // 2 x 64
    float* psum = pmax + 128;           // 2 x 64
    float* Ks   = psum + 128;           // max(S*KSTR, 64*PSTR)
    float* Ps   = Ks;                   // alias (Ks dead after QK)

    int h   = blockIdx.y;
    int grp = blockIdx.z;
    int i0  = blockIdx.x * 64;
    const float* base = qkv + (size_t)grp * groupStride;
    const float* qb = base + h * 64;
    const float* kb = base + 768 + h * 64;
    const float* vb = base + 1536 + h * 64;
    int tid = threadIdx.x;

    // ---- load K, V, Q tiles ----
    for (int idx = tid; idx < S * 16; idx += 256) {
        int j = idx >> 4, c4 = (idx & 15) << 2;
        float4 k4 = *(const float4*)(kb + (size_t)j * posStride + c4);
        float4 v4 = *(const float4*)(vb + (size_t)j * posStride + c4);
        float* kd = &Ks[j * KSTR + c4];
        kd[0] = k4.x; kd[1] = k4.y; kd[2] = k4.z; kd[3] = k4.w;
        float* vd = &Vs[j * VSTR + c4];
        vd[0] = v4.x; vd[1] = v4.y; vd[2] = v4.z; vd[3] = v4.w;
    }
    for (int idx = tid; idx < 64 * 16; idx += 256) {
        int i = idx >> 4, c4 = (idx & 15) << 2;
        float4 q4 = *(const float4*)(qb + (size_t)(i0 + i) * posStride + c4);
        float* qd = &Qs[i * QSTR + c4];
        qd[0] = q4.x * 0.125f; qd[1] = q4.y * 0.125f;
        qd[2] = q4.z * 0.125f; qd[3] = q4.w * 0.125f;
    }
    if (tid < S) negs[tid] = neg[(size_t)grp * negGroupStride + (size_t)tid * negStride];
    __syncthreads();

    int w = tid >> 5, lane = tid & 31;
    int r0 = lane >> 2, c0 = lane & 3;
    int wr = w & 3;                     // row quarter (16 rows)
    int sh = w >> 2;                    // key half / dim half
    int colbase = sh * HS;
    int rowA = wr * 16 + r0;

    // ---- QK^T scores ----
    float acc[NT][4];
#pragma unroll
    for (int nt = 0; nt < NT; nt++)
#pragma unroll
        for (int q = 0; q < 4; q++) acc[nt][q] = 0.0f;

#pragma unroll
    for (int kc = 0; kc < 8; kc++) {
        int k0 = kc * 8;
        uint32_t a0 = f2tf(Qs[rowA * QSTR + k0 + c0]);
        uint32_t a1 = f2tf(Qs[(rowA + 8) * QSTR + k0 + c0]);
        uint32_t a2 = f2tf(Qs[rowA * QSTR + k0 + c0 + 4]);
        uint32_t a3 = f2tf(Qs[(rowA + 8) * QSTR + k0 + c0 + 4]);
#pragma unroll
        for (int nt = 0; nt < NT; nt++) {
            int j = colbase + nt * 8 + r0;
            uint32_t b0 = f2tf(Ks[j * KSTR + k0 + c0]);
            uint32_t b1 = f2tf(Ks[j * KSTR + k0 + c0 + 4]);
            mma8(acc[nt], a0, a1, a2, a3, b0, b1);
        }
    }

    // ---- mask + row max (local to this key-half) ----
    float mlo = -3.4e38f, mhi = -3.4e38f;
#pragma unroll
    for (int nt = 0; nt < NT; nt++) {
        int cA = colbase + nt * 8 + c0 * 2;
        float n0v = negs[cA], n1v = negs[cA + 1];
        acc[nt][0] += n0v; acc[nt][1] += n1v;
        acc[nt][2] += n0v; acc[nt][3] += n1v;
        mlo = fmaxf(mlo, fmaxf(acc[nt][0], acc[nt][1]));
        mhi = fmaxf(mhi, fmaxf(acc[nt][2], acc[nt][3]));
    }
#pragma unroll
    for (int o = 1; o <= 2; o <<= 1) {
        mlo = fmaxf(mlo, __shfl_xor_sync(0xffffffffu, mlo, o));
        mhi = fmaxf(mhi, __shfl_xor_sync(0xffffffffu, mhi, o));
    }
    if (c0 == 0) {
        pmax[sh * 64 + wr * 16 + r0] = mlo;
        pmax[sh * 64 + wr * 16 + r0 + 8] = mhi;
    }
    __syncthreads();

    // ---- global max, exp, local sum, write P ----
    float gmlo = fmaxf(pmax[wr * 16 + r0], pmax[64 + wr * 16 + r0]);
    float gmhi = fmaxf(pmax[wr * 16 + r0 + 8], pmax[64 + wr * 16 + r0 + 8]);
    float slo = 0.0f, shi2 = 0.0f;
#pragma unroll
    for (int nt = 0; nt < NT; nt++) {
        acc[nt][0] = __expf(acc[nt][0] - gmlo);
        acc[nt][1] = __expf(acc[nt][1] - gmlo);
        acc[nt][2] = __expf(acc[nt][2] - gmhi);
        acc[nt][3] = __expf(acc[nt][3] - gmhi);
        slo += acc[nt][0] + acc[nt][1];
        shi2 += acc[nt][2] + acc[nt][3];
    }
#pragma unroll
    for (int o = 1; o <= 2; o <<= 1) {
        slo += __shfl_xor_sync(0xffffffffu, slo, o);
        shi2 += __shfl_xor_sync(0xffffffffu, shi2, o);
    }
    if (c0 == 0) {
        psum[sh * 64 + wr * 16 + r0] = slo;
        psum[sh * 64 + wr * 16 + r0 + 8] = shi2;
    }
#pragma unroll
    for (int nt = 0; nt < NT; nt++) {
        int cA = colbase + nt * 8 + c0 * 2;
        *(float2*)&Ps[(wr * 16 + r0) * PSTR + cA] = make_float2(acc[nt][0], acc[nt][1]);
        *(float2*)&Ps[(wr * 16 + r0 + 8) * PSTR + cA] = make_float2(acc[nt][2], acc[nt][3]);
    }
    __syncthreads();

    // ---- PV: out[16 rows][32 dims] per warp, K = S ----
    float oacc[4][4];
#pragma unroll
    for (int nt = 0; nt < 4; nt++)
#pragma unroll
        for (int q = 0; q < 4; q++) oacc[nt][q] = 0.0f;

#pragma unroll 4
    for (int kc = 0; kc < S / 8; kc++) {
        int k0 = kc * 8;
        uint32_t a0 = f2tf(Ps[rowA * PSTR + k0 + c0]);
        uint32_t a1 = f2tf(Ps[(rowA + 8) * PSTR + k0 + c0]);
        uint32_t a2 = f2tf(Ps[rowA * PSTR + k0 + c0 + 4]);
        uint32_t a3 = f2tf(Ps[(rowA + 8) * PSTR + k0 + c0 + 4]);
#pragma unroll
        for (int nt = 0; nt < 4; nt++) {
            int d = sh * 32 + nt * 8 + r0;
            uint32_t b0 = f2tf(Vs[(k0 + c0) * VSTR + d]);
            uint32_t b1 = f2tf(Vs[(k0 + c0 + 4) * VSTR + d]);
            mma8(oacc[nt], a0, a1, a2, a3, b0, b1);
        }
    }

    // ---- epilogue: scale by 1/sum, store ----
    float rlo = 1.0f / (psum[wr * 16 + r0] + psum[64 + wr * 16 + r0]);
    float rhi = 1.0f / (psum[wr * 16 + r0 + 8] + psum[64 + wr * 16 + r0 + 8]);
#pragma unroll
    for (int nt = 0; nt < 4; nt++) {
        int d = sh * 32 + nt * 8 + c0 * 2;
        float* olo = outp + (size_t)grp * outGroupStride
                   + (size_t)(i0 + wr * 16 + r0) * outPosStride + h * 64 + d;
        float* ohi = outp + (size_t)grp * outGroupStride
                   + (size_t)(i0 + wr * 16 + r0 + 8) * outPosStride + h * 64 + d;
        *(float2*)olo = make_float2(oacc[nt][0] * rlo, oacc[nt][1] * rlo);
        *(float2*)ohi = make_float2(oacc[nt][2] * rhi, oacc[nt][3] * rhi);
    }
}

// smem sizes (floats): Vs + Qs + negs + stats + max(Ks, Ps)
#define ATTN_SMEM(S) ((S * VSTR + 64 * QSTR + S + 256 + \
                      ((S * KSTR > 64 * PSTR) ? S * KSTR : 64 * PSTR)) * 4)

// ------------------------- residual + LayerNorm -------------------------
__global__ __launch_bounds__(256)
void ln_kernel(const float* __restrict__ x, const float* __restrict__ r,
               const float* __restrict__ g, const float* __restrict__ b,
               float* __restrict__ out) {
    __shared__ float rs[8], rq[8], sh[2];
    int row = blockIdx.x, tid = threadIdx.x;
    size_t b0 = (size_t)row * DD;
    float v[3]; float s = 0.0f, q = 0.0f;
#pragma unroll
    for (int u = 0; u < 3; u++) {
        int c = tid + u * 256;
        float t = x[b0 + c] + r[b0 + c];
        v[u] = t; s += t; q += t * t;
    }
#pragma unroll
    for (int o = 16; o > 0; o >>= 1) {
        s += __shfl_down_sync(0xffffffffu, s, o);
        q += __shfl_down_sync(0xffffffffu, q, o);
    }
    int wid = tid >> 5, lane = tid & 31;
    if (lane == 0) { rs[wid] = s; rq[wid] = q; }
    __syncthreads();
    if (tid == 0) {
        float S = 0.0f, Q = 0.0f;
#pragma unroll
        for (int w = 0; w < 8; w++) { S += rs[w]; Q += rq[w]; }
        float mu = S * (1.0f / 768.0f);
        sh[0] = mu;
        sh[1] = rsqrtf(Q * (1.0f / 768.0f) - mu * mu + 1e-5f);
    }
    __syncthreads();
    float mu = sh[0], inv = sh[1];
#pragma unroll
    for (int u = 0; u < 3; u++) {
        int c = tid + u * 256;
        out[b0 + c] = (v[u] - mu) * inv * g[c] + b[c];
    }
}

// ------------------------- launch -------------------------
extern "C" void kernel_launch(void* const* d_in, const int* in_sizes, int n_in,
                              void* d_out, int out_size) {
    const float* x     = (const float*)d_in[0];
    const float* w_row = (const float*)d_in[1];
    const float* b_row = (const float*)d_in[2];
    const float* w_col = (const float*)d_in[3];
    const float* b_col = (const float*)d_in[4];
    const float* g1    = (const float*)d_in[5];
    const float* be1   = (const float*)d_in[6];
    const float* g2    = (const float*)d_in[7];
    const float* be2   = (const float*)d_in[8];
    const void*  mask  = d_in[9];
    float* out = (float*)d_out;

    float *qkv, *tmp, *neg;
    cudaGetSymbolAddress((void**)&qkv, g_qkv);
    cudaGetSymbolAddress((void**)&tmp, g_tmp);
    cudaGetSymbolAddress((void**)&neg, g_neg);

    cudaFuncSetAttribute(attn_tc_kernel<256>, cudaFuncAttributeMaxDynamicSharedMemorySize, ATTN_SMEM(256));
    cudaFuncSetAttribute(attn_tc_kernel<128>, cudaFuncAttributeMaxDynamicSharedMemorySize, ATTN_SMEM(128));
    cudaFuncSetAttribute(gemm_mma_kernel, cudaFuncAttributeMaxDynamicSharedMemorySize, GEMM_SMEM);

    neg_kernel<<<1, 256>>>(mask);

    dim3 ggrid(D3 / GN, NROWS / GM);   // (9, 256)

    // ---- row attention block ----
    gemm_mma_kernel<<<ggrid, 256, GEMM_SMEM>>>(x, w_row, b_row, qkv);
    {
        dim3 agrid(LL / 64, 12, EE);
        attn_tc_kernel<256><<<agrid, 256, ATTN_SMEM(256)>>>(
            qkv, (long)LL * D3, (long)D3,
            neg, (long)LL, 1L,
            tmp, (long)LL * DD, (long)DD);
    }
    ln_kernel<<<NROWS, 256>>>(x, tmp, g1, be1, out);

    // ---- column attention block ----
    gemm_mma_kernel<<<ggrid, 256, GEMM_SMEM>>>(out, w_col, b_col, qkv);
    {
        dim3 agrid(EE / 64, 12, LL);
        attn_tc_kernel<128><<<agrid, 256, ATTN_SMEM(128)>>>(
            qkv, (long)D3, (long)LL * D3,
            neg, 1L, (long)LL,
            tmp, (long)DD, (long)LL * DD);
    }
    ln_kernel<<<NROWS, 256>>>(out, tmp, g2, be2, out);
}

// round 6
// speedup vs baseline: 2.4658x; 1.0414x over previous
#include <cuda_runtime.h>
#include <cuda_bf16.h>
#include <stdint.h>
#include <math.h>

// Problem constants: B=1, E=128, L=256, D=768, H=12, DH=64
#define EE 128
#define LL 256
#define DD 768
#define D3 2304
#define NROWS 32768          // E*L
#define NEGV (-10000.0f)

typedef unsigned long long ull;

// ------------------------- scratch (static device globals; no runtime alloc) -------------------------
__device__ float g_qkv[(size_t)NROWS * D3];   // 302 MB (tf32-rounded by GEMM epilogue)
__device__ float g_tmp[(size_t)NROWS * DD];   // 100 MB
__device__ float g_acv[(size_t)NROWS * DD];   // 100 MB (tf32-rounded activations)
__device__ float g_wcv[(size_t)D3 * DD];      // 7 MB  (tf32-rounded weights)
__device__ float g_neg[NROWS];

// ------------------------- PTX helpers -------------------------
__device__ __forceinline__ uint32_t smem_u32(const void* p) {
    uint32_t a;
    asm("{ .reg .u64 t; cvta.to.shared.u64 t, %1; cvt.u32.u64 %0, t; }" : "=r"(a) : "l"(p));
    return a;
}
__device__ __forceinline__ void cp_async16(uint32_t dst, const void* src) {
    asm volatile("cp.async.cg.shared.global [%0], [%1], 16;" :: "r"(dst), "l"(src) : "memory");
}
__device__ __forceinline__ uint32_t f2tf(float f) {
    uint32_t r; asm("cvt.rna.tf32.f32 %0, %1;" : "=r"(r) : "f"(f)); return r;
}
__device__ __forceinline__ void mma8(float* c, uint32_t a0, uint32_t a1, uint32_t a2, uint32_t a3,
                                     uint32_t b0, uint32_t b1) {
    asm volatile(
        "mma.sync.aligned.m16n8k8.row.col.f32.tf32.tf32.f32 "
        "{%0,%1,%2,%3}, {%4,%5,%6,%7}, {%8,%9}, {%0,%1,%2,%3};"
        : "+f"(c[0]), "+f"(c[1]), "+f"(c[2]), "+f"(c[3])
        : "r"(a0), "r"(a1), "r"(a2), "r"(a3), "r"(b0), "r"(b1));
}

// ------------------------- padding mask -> additive neg, with dtype auto-detect -------------------------
__global__ void neg_kernel(const void* mraw) {
    __shared__ int notInt, notFloat;
    int tid = threadIdx.x;
    if (tid == 0) { notInt = 0; notFloat = 0; }
    __syncthreads();
    const unsigned int* w = (const unsigned int*)mraw;
    int badI = 0, badF = 0;
    for (int i = tid; i < 8192; i += 256) {
        unsigned int v = w[i];
        if (v > 1u) badI = 1;
        if (v != 0u && v != 0x3F800000u) badF = 1;
    }
    if (badI) notInt = 1;
    if (badF) notFloat = 1;
    __syncthreads();
    int mode = (!notInt) ? 0 : ((!notFloat) ? 1 : 2);  // 0=int32, 1=float32, 2=uint8
    for (int i = tid; i < NROWS; i += 256) {
        bool m;
        if (mode == 0)      m = ((const int*)mraw)[i] != 0;
        else if (mode == 1) m = ((const float*)mraw)[i] != 0.0f;
        else                m = ((const unsigned char*)mraw)[i] != 0;
        g_neg[i] = m ? NEGV : 0.0f;
    }
}

// ------------------------- fp32 -> tf32 (rna) pre-pass -------------------------
__global__ __launch_bounds__(256)
void cvt_tf32_kernel(const float* __restrict__ in, float* __restrict__ out) {
    size_t i = ((size_t)blockIdx.x * 256 + threadIdx.x) * 4;
    float4 v = *(const float4*)(in + i);
    *(uint4*)(out + i) = make_uint4(f2tf(v.x), f2tf(v.y), f2tf(v.z), f2tf(v.w));
}

// ------------------------- tf32 mma.sync GEMM: C[M,2304] = A[M,768] @ W[2304,768]^T + bias -------------------------
// Inputs pre-rounded to tf32; mainloop has zero cvt. Epilogue writes tf32-rounded C.
#define GM 128
#define GN 256
#define KB 32
#define NST 24                       // 768/32
#define ASTR 36
#define AFLOATS (128 * ASTR)         // 4608
#define BFLOATS (256 * ASTR)         // 9216
#define STAGEF (AFLOATS + BFLOATS)   // 13824 floats
#define GEMM_SMEM (3 * STAGEF * 4)   // 165888 bytes

__device__ __forceinline__ void load_stage(float* sm, int stg, const float* Ab, const float* Wb,
                                           int k0, int tid) {
    float* As = sm + stg * STAGEF;
    float* Bs = As + AFLOATS;
    uint32_t as_u = smem_u32(As), bs_u = smem_u32(Bs);
#pragma unroll
    for (int i = 0; i < 4; i++) {
        int idx = tid + i * 256;
        int row = idx >> 3, ch = idx & 7;
        cp_async16(as_u + row * (ASTR * 4) + ch * 16, Ab + (size_t)row * DD + k0 + ch * 4);
    }
#pragma unroll
    for (int i = 0; i < 8; i++) {
        int idx = tid + i * 256;
        int row = idx >> 3, ch = idx & 7;
        cp_async16(bs_u + row * (ASTR * 4) + ch * 16, Wb + (size_t)row * DD + k0 + ch * 4);
    }
}

__global__ __launch_bounds__(256, 1)
void gemm_mma_kernel(const float* __restrict__ A, const float* __restrict__ W,
                     const float* __restrict__ bias, float* __restrict__ C) {
    extern __shared__ float sm[];
    int tid = threadIdx.x, lane = tid & 31, w = tid >> 5;
    int wm = w & 1, wn = w >> 1;
    int m0 = blockIdx.y * GM, n0 = blockIdx.x * GN;
    const float* Ab = A + (size_t)m0 * DD;
    const float* Wb = W + (size_t)n0 * DD;
    int r0 = lane >> 2, c0 = lane & 3;

    float acc[4][8][4];
#pragma unroll
    for (int mt = 0; mt < 4; mt++)
#pragma unroll
        for (int nt = 0; nt < 8; nt++)
#pragma unroll
            for (int q = 0; q < 4; q++) acc[mt][nt][q] = 0.0f;

    load_stage(sm, 0, Ab, Wb, 0, tid);
    asm volatile("cp.async.commit_group;" ::: "memory");
    load_stage(sm, 1, Ab, Wb, KB, tid);
    asm volatile("cp.async.commit_group;" ::: "memory");

    for (int s = 0; s < NST; ++s) {
        int b = s % 3;
        asm volatile("cp.async.wait_group 1;" ::: "memory");
        __syncthreads();
        if (s + 2 < NST) load_stage(sm, (s + 2) % 3, Ab, Wb, (s + 2) * KB, tid);
        asm volatile("cp.async.commit_group;" ::: "memory");

        const uint32_t* As = (const uint32_t*)(sm + b * STAGEF);
        const uint32_t* Bs = As + AFLOATS;
#pragma unroll
        for (int ks = 0; ks < 4; ks++) {
            int K0 = ks * 8 + c0;
            uint32_t bf[8][2];
#pragma unroll
            for (int nt = 0; nt < 8; nt++) {
                int N0 = wn * 64 + nt * 8 + r0;
                bf[nt][0] = Bs[N0 * ASTR + K0];
                bf[nt][1] = Bs[N0 * ASTR + K0 + 4];
            }
#pragma unroll
            for (int mt = 0; mt < 4; mt++) {
                int R = wm * 64 + mt * 16 + r0;
                uint32_t a0 = As[R * ASTR + K0];
                uint32_t a1 = As[(R + 8) * ASTR + K0];
                uint32_t a2 = As[R * ASTR + K0 + 4];
                uint32_t a3 = As[(R + 8) * ASTR + K0 + 4];
#pragma unroll
                for (int nt = 0; nt < 8; nt++)
                    mma8(acc[mt][nt], a0, a1, a2, a3, bf[nt][0], bf[nt][1]);
            }
        }
    }
    asm volatile("cp.async.wait_group 0;" ::: "memory");

    // epilogue: add bias, round to tf32 (attention consumes tf32 anyway)
#pragma unroll
    for (int nt = 0; nt < 8; nt++) {
        int col = n0 + wn * 64 + nt * 8 + c0 * 2;
        float b0v = bias[col], b1v = bias[col + 1];
#pragma unroll
        for (int mt = 0; mt < 4; mt++) {
            int row = m0 + wm * 64 + mt * 16 + r0;
            uint2 v0 = make_uint2(f2tf(acc[mt][nt][0] + b0v), f2tf(acc[mt][nt][1] + b1v));
            uint2 v1 = make_uint2(f2tf(acc[mt][nt][2] + b0v), f2tf(acc[mt][nt][3] + b1v));
            *(uint2*)&C[(size_t)row * D3 + col] = v0;
            *(uint2*)&C[(size_t)(row + 8) * D3 + col] = v1;
        }
    }
}

// ------------------------- tensor-core attention (inputs already tf32-rounded) -------------------------
#define QSTR 68
#define KSTR 68
#define VSTR 72
#define PSTR 260

template<int S>
__global__ __launch_bounds__(256)
void attn_tc_kernel(const float* __restrict__ qkv,
                    long groupStride, long posStride,
                    const float* __restrict__ neg, long negGroupStride, long negStride,
                    float* __restrict__ outp, long outGroupStride, long outPosStride) {
    constexpr int HS = S / 2;
    constexpr int NT = HS / 8;
    extern __shared__ float smf[];
    float* Vs   = smf;                  // S x VSTR
    float* Qs   = Vs + S * VSTR;        // 64 x QSTR
    float* negs = Qs + 64 * QSTR;       // S
    float* pmax = negs + S;             // 2 x 64
    float* psum = pmax + 128;           // 2 x 64
    float* Ks   = psum + 128;           // max(S*KSTR, 64*PSTR)
    float* Ps   = Ks;                   // alias (Ks dead after QK)

    int h   = blockIdx.y;
    int grp = blockIdx.z;
    int i0  = blockIdx.x * 64;
    const float* base = qkv + (size_t)grp * groupStride;
    const float* qb = base + h * 64;
    const float* kb = base + 768 + h * 64;
    const float* vb = base + 1536 + h * 64;
    int tid = threadIdx.x;

    for (int idx = tid; idx < S * 16; idx += 256) {
        int j = idx >> 4, c4 = (idx & 15) << 2;
        float4 k4 = *(const float4*)(kb + (size_t)j * posStride + c4);
        float4 v4 = *(const float4*)(vb + (size_t)j * posStride + c4);
        float* kd = &Ks[j * KSTR + c4];
        kd[0] = k4.x; kd[1] = k4.y; kd[2] = k4.z; kd[3] = k4.w;
        float* vd = &Vs[j * VSTR + c4];
        vd[0] = v4.x; vd[1] = v4.y; vd[2] = v4.z; vd[3] = v4.w;
    }
    for (int idx = tid; idx < 64 * 16; idx += 256) {
        int i = idx >> 4, c4 = (idx & 15) << 2;
        float4 q4 = *(const float4*)(qb + (size_t)(i0 + i) * posStride + c4);
        float* qd = &Qs[i * QSTR + c4];
        qd[0] = q4.x * 0.125f; qd[1] = q4.y * 0.125f;    // exponent-only scale: stays tf32
        qd[2] = q4.z * 0.125f; qd[3] = q4.w * 0.125f;
    }
    if (tid < S) negs[tid] = neg[(size_t)grp * negGroupStride + (size_t)tid * negStride];
    __syncthreads();

    int w = tid >> 5, lane = tid & 31;
    int r0 = lane >> 2, c0 = lane & 3;
    int wr = w & 3;
    int sh = w >> 2;
    int colbase = sh * HS;
    int rowA = wr * 16 + r0;

    const uint32_t* Qu = (const uint32_t*)Qs;
    const uint32_t* Ku = (const uint32_t*)Ks;
    const uint32_t* Vu = (const uint32_t*)Vs;

    // ---- QK^T scores (no cvt: data already tf32) ----
    float acc[NT][4];
#pragma unroll
    for (int nt = 0; nt < NT; nt++)
#pragma unroll
        for (int q = 0; q < 4; q++) acc[nt][q] = 0.0f;

#pragma unroll
    for (int kc = 0; kc < 8; kc++) {
        int k0 = kc * 8;
        uint32_t a0 = Qu[rowA * QSTR + k0 + c0];
        uint32_t a1 = Qu[(rowA + 8) * QSTR + k0 + c0];
        uint32_t a2 = Qu[rowA * QSTR + k0 + c0 + 4];
        uint32_t a3 = Qu[(rowA + 8) * QSTR + k0 + c0 + 4];
#pragma unroll
        for (int nt = 0; nt < NT; nt++) {
            int j = colbase + nt * 8 + r0;
            uint32_t b0 = Ku[j * KSTR + k0 + c0];
            uint32_t b1 = Ku[j * KSTR + k0 + c0 + 4];
            mma8(acc[nt], a0, a1, a2, a3, b0, b1);
        }
    }

    // ---- mask + row max (local to this key-half) ----
    float mlo = -3.4e38f, mhi = -3.4e38f;
#pragma unroll
    for (int nt = 0; nt < NT; nt++) {
        int cA = colbase + nt * 8 + c0 * 2;
        float n0v = negs[cA], n1v = negs[cA + 1];
        acc[nt][0] += n0v; acc[nt][1] += n1v;
        acc[nt][2] += n0v; acc[nt][3] += n1v;
        mlo = fmaxf(mlo, fmaxf(acc[nt][0], acc[nt][1]));
        mhi = fmaxf(mhi, fmaxf(acc[nt][2], acc[nt][3]));
    }
#pragma unroll
    for (int o = 1; o <= 2; o <<= 1) {
        mlo = fmaxf(mlo, __shfl_xor_sync(0xffffffffu, mlo, o));
        mhi = fmaxf(mhi, __shfl_xor_sync(0xffffffffu, mhi, o));
    }
    if (c0 == 0) {
        pmax[sh * 64 + wr * 16 + r0] = mlo;
        pmax[sh * 64 + wr * 16 + r0 + 8] = mhi;
    }
    __syncthreads();

    // ---- global max, exp, local sum, write P ----
    float gmlo = fmaxf(pmax[wr * 16 + r0], pmax[64 + wr * 16 + r0]);
    float gmhi = fmaxf(pmax[wr * 16 + r0 + 8], pmax[64 + wr * 16 + r0 + 8]);
    float slo = 0.0f, shi2 = 0.0f;
#pragma unroll
    for (int nt = 0; nt < NT; nt++) {
        acc[nt][0] = __expf(acc[nt][0] - gmlo);
        acc[nt][1] = __expf(acc[nt][1] - gmlo);
        acc[nt][2] = __expf(acc[nt][2] - gmhi);
        acc[nt][3] = __expf(acc[nt][3] - gmhi);
        slo += acc[nt][0] + acc[nt][1];
        shi2 += acc[nt][2] + acc[nt][3];
    }
#pragma unroll
    for (int o = 1; o <= 2; o <<= 1) {
        slo += __shfl_xor_sync(0xffffffffu, slo, o);
        shi2 += __shfl_xor_sync(0xffffffffu, shi2, o);
    }
    if (c0 == 0) {
        psum[sh * 64 + wr * 16 + r0] = slo;
        psum[sh * 64 + wr * 16 + r0 + 8] = shi2;
    }
    // write P already tf32-rounded so PV loop needs no cvt
#pragma unroll
    for (int nt = 0; nt < NT; nt++) {
        int cA = colbase + nt * 8 + c0 * 2;
        *(uint2*)&Ps[(wr * 16 + r0) * PSTR + cA] =
            make_uint2(f2tf(acc[nt][0]), f2tf(acc[nt][1]));
        *(uint2*)&Ps[(wr * 16 + r0 + 8) * PSTR + cA] =
            make_uint2(f2tf(acc[nt][2]), f2tf(acc[nt][3]));
    }
    __syncthreads();

    // ---- PV: out[16 rows][32 dims] per warp, K = S ----
    const uint32_t* Pu = (const uint32_t*)Ps;
    float oacc[4][4];
#pragma unroll
    for (int nt = 0; nt < 4; nt++)
#pragma unroll
        for (int q = 0; q < 4; q++) oacc[nt][q] = 0.0f;

#pragma unroll 4
    for (int kc = 0; kc < S / 8; kc++) {
        int k0 = kc * 8;
        uint32_t a0 = Pu[rowA * PSTR + k0 + c0];
        uint32_t a1 = Pu[(rowA + 8) * PSTR + k0 + c0];
        uint32_t a2 = Pu[rowA * PSTR + k0 + c0 + 4];
        uint32_t a3 = Pu[(rowA + 8) * PSTR + k0 + c0 + 4];
#pragma unroll
        for (int nt = 0; nt < 4; nt++) {
            int d = sh * 32 + nt * 8 + r0;
            uint32_t b0 = Vu[(k0 + c0) * VSTR + d];
            uint32_t b1 = Vu[(k0 + c0 + 4) * VSTR + d];
            mma8(oacc[nt], a0, a1, a2, a3, b0, b1);
        }
    }

    // ---- epilogue: scale by 1/sum, store ----
    float rlo = 1.0f / (psum[wr * 16 + r0] + psum[64 + wr * 16 + r0]);
    float rhi = 1.0f / (psum[wr * 16 + r0 + 8] + psum[64 + wr * 16 + r0 + 8]);
#pragma unroll
    for (int nt = 0; nt < 4; nt++) {
        int d = sh * 32 + nt * 8 + c0 * 2;
        float* olo = outp + (size_t)grp * outGroupStride
                   + (size_t)(i0 + wr * 16 + r0) * outPosStride + h * 64 + d;
        float* ohi = outp + (size_t)grp * outGroupStride
                   + (size_t)(i0 + wr * 16 + r0 + 8) * outPosStride + h * 64 + d;
        *(float2*)olo = make_float2(oacc[nt][0] * rlo, oacc[nt][1] * rlo);
        *(float2*)ohi = make_float2(oacc[nt][2] * rhi, oacc[nt][3] * rhi);
    }
}

#define ATTN_SMEM(S) ((S * VSTR + 64 * QSTR + S + 256 + \
                      ((S * KSTR > 64 * PSTR) ? S * KSTR : 64 * PSTR)) * 4)

// ------------------------- residual + LayerNorm -------------------------
__global__ __launch_bounds__(256)
void ln_kernel(const float* __restrict__ x, const float* __restrict__ r,
               const float* __restrict__ g, const float* __restrict__ b,
               float* __restrict__ out) {
    __shared__ float rs[8], rq[8], sh[2];
    int row = blockIdx.x, tid = threadIdx.x;
    size_t b0 = (size_t)row * DD;
    float v[3]; float s = 0.0f, q = 0.0f;
#pragma unroll
    for (int u = 0; u < 3; u++) {
        int c = tid + u * 256;
        float t = x[b0 + c] + r[b0 + c];
        v[u] = t; s += t; q += t * t;
    }
#pragma unroll
    for (int o = 16; o > 0; o >>= 1) {
        s += __shfl_down_sync(0xffffffffu, s, o);
        q += __shfl_down_sync(0xffffffffu, q, o);
    }
    int wid = tid >> 5, lane = tid & 31;
    if (lane == 0) { rs[wid] = s; rq[wid] = q; }
    __syncthreads();
    if (tid == 0) {
        float S = 0.0f, Q = 0.0f;
#pragma unroll
        for (int w = 0; w < 8; w++) { S += rs[w]; Q += rq[w]; }
        float mu = S * (1.0f / 768.0f);
        sh[0] = mu;
        sh[1] = rsqrtf(Q * (1.0f / 768.0f) - mu * mu + 1e-5f);
    }
    __syncthreads();
    float mu = sh[0], inv = sh[1];
#pragma unroll
    for (int u = 0; u < 3; u++) {
        int c = tid + u * 256;
        out[b0 + c] = (v[u] - mu) * inv * g[c] + b[c];
    }
}

// ------------------------- launch -------------------------
extern "C" void kernel_launch(void* const* d_in, const int* in_sizes, int n_in,
                              void* d_out, int out_size) {
    const float* x     = (const float*)d_in[0];
    const float* w_row = (const float*)d_in[1];
    const float* b_row = (const float*)d_in[2];
    const float* w_col = (const float*)d_in[3];
    const float* b_col = (const float*)d_in[4];
    const float* g1    = (const float*)d_in[5];
    const float* be1   = (const float*)d_in[6];
    const float* g2    = (const float*)d_in[7];
    const float* be2   = (const float*)d_in[8];
    const void*  mask  = d_in[9];
    float* out = (float*)d_out;

    float *qkv, *tmp, *acv, *wcv, *neg;
    cudaGetSymbolAddress((void**)&qkv, g_qkv);
    cudaGetSymbolAddress((void**)&tmp, g_tmp);
    cudaGetSymbolAddress((void**)&acv, g_acv);
    cudaGetSymbolAddress((void**)&wcv, g_wcv);
    cudaGetSymbolAddress((void**)&neg, g_neg);

    cudaFuncSetAttribute(attn_tc_kernel<256>, cudaFuncAttributeMaxDynamicSharedMemorySize, ATTN_SMEM(256));
    cudaFuncSetAttribute(attn_tc_kernel<128>, cudaFuncAttributeMaxDynamicSharedMemorySize, ATTN_SMEM(128));
    cudaFuncSetAttribute(gemm_mma_kernel, cudaFuncAttributeMaxDynamicSharedMemorySize, GEMM_SMEM);

    neg_kernel<<<1, 256>>>(mask);

    dim3 ggrid(D3 / GN, NROWS / GM);   // (9, 256)
    const int ACV_BLKS = (int)(((size_t)NROWS * DD) / 1024);   // 24576
    const int WCV_BLKS = (int)(((size_t)D3 * DD) / 1024);      // 1728

    // ---- row attention block ----
    cvt_tf32_kernel<<<ACV_BLKS, 256>>>(x, acv);
    cvt_tf32_kernel<<<WCV_BLKS, 256>>>(w_row, wcv);
    gemm_mma_kernel<<<ggrid, 256, GEMM_SMEM>>>(acv, wcv, b_row, qkv);
    {
        dim3 agrid(LL / 64, 12, EE);
        attn_tc_kernel<256><<<agrid, 256, ATTN_SMEM(256)>>>(
            qkv, (long)LL * D3, (long)D3,
            neg, (long)LL, 1L,
            tmp, (long)LL * DD, (long)DD);
    }
    ln_kernel<<<NROWS, 256>>>(x, tmp, g1, be1, out);

    // ---- column attention block ----
    cvt_tf32_kernel<<<ACV_BLKS, 256>>>(out, acv);
    cvt_tf32_kernel<<<WCV_BLKS, 256>>>(w_col, wcv);
    gemm_mma_kernel<<<ggrid, 256, GEMM_SMEM>>>(acv, wcv, b_col, qkv);
    {
        dim3 agrid(EE / 64, 12, LL);
        attn_tc_kernel<128><<<agrid, 256, ATTN_SMEM(128)>>>(
            qkv, (long)D3, (long)LL * D3,
            neg, 1L, (long)LL,
            tmp, (long)DD, (long)LL * DD);
    }
    ln_kernel<<<NROWS, 256>>>(out, tmp, g2, be2, out);
}

// round 7
// speedup vs baseline: 2.5252x; 1.0241x over previous
#include <cuda_runtime.h>
#include <cuda_bf16.h>
#include <stdint.h>
#include <math.h>

// Problem constants: B=1, E=128, L=256, D=768, H=12, DH=64
#define EE 128
#define LL 256
#define DD 768
#define D3 2304
#define NROWS 32768          // E*L
#define NEGV (-10000.0f)

typedef unsigned long long ull;

// ------------------------- scratch (static device globals; no runtime alloc) -------------------------
__device__ float g_qkv[(size_t)NROWS * D3];   // 302 MB (tf32-rounded by GEMM epilogue)
__device__ float g_tmp[(size_t)NROWS * DD];   // 100 MB
__device__ float g_acv[(size_t)NROWS * DD];   // 100 MB (tf32-rounded activations)
__device__ float g_wcv[(size_t)D3 * DD];      // 7 MB  (tf32-rounded weights)
__device__ float g_neg[NROWS];

// ------------------------- PTX helpers -------------------------
__device__ __forceinline__ uint32_t smem_u32(const void* p) {
    uint32_t a;
    asm("{ .reg .u64 t; cvta.to.shared.u64 t, %1; cvt.u32.u64 %0, t; }" : "=r"(a) : "l"(p));
    return a;
}
__device__ __forceinline__ void cp_async16(uint32_t dst, const void* src) {
    asm volatile("cp.async.cg.shared.global [%0], [%1], 16;" :: "r"(dst), "l"(src) : "memory");
}
__device__ __forceinline__ uint32_t f2tf(float f) {
    uint32_t r; asm("cvt.rna.tf32.f32 %0, %1;" : "=r"(r) : "f"(f)); return r;
}
__device__ __forceinline__ void mma8(float* c, uint32_t a0, uint32_t a1, uint32_t a2, uint32_t a3,
                                     uint32_t b0, uint32_t b1) {
    asm volatile(
        "mma.sync.aligned.m16n8k8.row.col.f32.tf32.tf32.f32 "
        "{%0,%1,%2,%3}, {%4,%5,%6,%7}, {%8,%9}, {%0,%1,%2,%3};"
        : "+f"(c[0]), "+f"(c[1]), "+f"(c[2]), "+f"(c[3])
        : "r"(a0), "r"(a1), "r"(a2), "r"(a3), "r"(b0), "r"(b1));
}

// ------------------------- padding mask -> additive neg, with dtype auto-detect -------------------------
__global__ void neg_kernel(const void* mraw) {
    __shared__ int notInt, notFloat;
    int tid = threadIdx.x;
    if (tid == 0) { notInt = 0; notFloat = 0; }
    __syncthreads();
    const unsigned int* w = (const unsigned int*)mraw;
    int badI = 0, badF = 0;
    for (int i = tid; i < 8192; i += 256) {
        unsigned int v = w[i];
        if (v > 1u) badI = 1;
        if (v != 0u && v != 0x3F800000u) badF = 1;
    }
    if (badI) notInt = 1;
    if (badF) notFloat = 1;
    __syncthreads();
    int mode = (!notInt) ? 0 : ((!notFloat) ? 1 : 2);  // 0=int32, 1=float32, 2=uint8
    for (int i = tid; i < NROWS; i += 256) {
        bool m;
        if (mode == 0)      m = ((const int*)mraw)[i] != 0;
        else if (mode == 1) m = ((const float*)mraw)[i] != 0.0f;
        else                m = ((const unsigned char*)mraw)[i] != 0;
        g_neg[i] = m ? NEGV : 0.0f;
    }
}

// ------------------------- fp32 -> tf32 (rna) pre-pass -------------------------
__global__ __launch_bounds__(256)
void cvt_tf32_kernel(const float* __restrict__ in, float* __restrict__ out) {
    size_t i = ((size_t)blockIdx.x * 256 + threadIdx.x) * 4;
    float4 v = *(const float4*)(in + i);
    *(uint4*)(out + i) = make_uint4(f2tf(v.x), f2tf(v.y), f2tf(v.z), f2tf(v.w));
}

// ------------------------- tf32 mma.sync GEMM: C[M,2304] = A[M,768] @ W[2304,768]^T + bias -------------------------
// CTA: 128 threads (4 warps), tile 128x128, warp tile 64x64, 3-stage cp.async,
// 2 CTAs/SM residency (110.6KB smem, <=256 regs).
#define GM 128
#define GN 128
#define KB 32
#define NST 24                       // 768/32
#define ASTR 36
#define AFLOATS (128 * ASTR)         // 4608
#define BFLOATS (128 * ASTR)         // 4608
#define STAGEF (AFLOATS + BFLOATS)   // 9216 floats
#define GEMM_SMEM (3 * STAGEF * 4)   // 110592 bytes

__device__ __forceinline__ void load_stage(float* sm, int stg, const float* Ab, const float* Wb,
                                           int k0, int tid) {
    float* As = sm + stg * STAGEF;
    float* Bs = As + AFLOATS;
    uint32_t as_u = smem_u32(As), bs_u = smem_u32(Bs);
#pragma unroll
    for (int i = 0; i < 8; i++) {            // A: 128 rows x 8 chunks of 16B, 128 threads
        int idx = tid + i * 128;
        int row = idx >> 3, ch = idx & 7;
        cp_async16(as_u + row * (ASTR * 4) + ch * 16, Ab + (size_t)row * DD + k0 + ch * 4);
    }
#pragma unroll
    for (int i = 0; i < 8; i++) {            // B: 128 rows x 8 chunks of 16B
        int idx = tid + i * 128;
        int row = idx >> 3, ch = idx & 7;
        cp_async16(bs_u + row * (ASTR * 4) + ch * 16, Wb + (size_t)row * DD + k0 + ch * 4);
    }
}

__global__ __launch_bounds__(128, 2)
void gemm_mma_kernel(const float* __restrict__ A, const float* __restrict__ W,
                     const float* __restrict__ bias, float* __restrict__ C) {
    extern __shared__ float sm[];
    int tid = threadIdx.x, lane = tid & 31, w = tid >> 5;
    int wm = w & 1, wn = w >> 1;              // warp grid 2 (m) x 2 (n)
    int m0 = blockIdx.y * GM, n0 = blockIdx.x * GN;
    const float* Ab = A + (size_t)m0 * DD;
    const float* Wb = W + (size_t)n0 * DD;
    int r0 = lane >> 2, c0 = lane & 3;

    float acc[4][8][4];
#pragma unroll
    for (int mt = 0; mt < 4; mt++)
#pragma unroll
        for (int nt = 0; nt < 8; nt++)
#pragma unroll
            for (int q = 0; q < 4; q++) acc[mt][nt][q] = 0.0f;

    load_stage(sm, 0, Ab, Wb, 0, tid);
    asm volatile("cp.async.commit_group;" ::: "memory");
    load_stage(sm, 1, Ab, Wb, KB, tid);
    asm volatile("cp.async.commit_group;" ::: "memory");

    for (int s = 0; s < NST; ++s) {
        int b = s % 3;
        asm volatile("cp.async.wait_group 1;" ::: "memory");
        __syncthreads();
        if (s + 2 < NST) load_stage(sm, (s + 2) % 3, Ab, Wb, (s + 2) * KB, tid);
        asm volatile("cp.async.commit_group;" ::: "memory");

        const uint32_t* As = (const uint32_t*)(sm + b * STAGEF);
        const uint32_t* Bs = As + AFLOATS;
#pragma unroll
        for (int ks = 0; ks < 4; ks++) {
            int K0 = ks * 8 + c0;
            uint32_t bf[8][2];
#pragma unroll
            for (int nt = 0; nt < 8; nt++) {
                int N0 = wn * 64 + nt * 8 + r0;
                bf[nt][0] = Bs[N0 * ASTR + K0];
                bf[nt][1] = Bs[N0 * ASTR + K0 + 4];
            }
#pragma unroll
            for (int mt = 0; mt < 4; mt++) {
                int R = wm * 64 + mt * 16 + r0;
                uint32_t a0 = As[R * ASTR + K0];
                uint32_t a1 = As[(R + 8) * ASTR + K0];
                uint32_t a2 = As[R * ASTR + K0 + 4];
                uint32_t a3 = As[(R + 8) * ASTR + K0 + 4];
#pragma unroll
                for (int nt = 0; nt < 8; nt++)
                    mma8(acc[mt][nt], a0, a1, a2, a3, bf[nt][0], bf[nt][1]);
            }
        }
    }
    asm volatile("cp.async.wait_group 0;" ::: "memory");

    // epilogue: add bias, round to tf32 (attention consumes tf32 anyway)
#pragma unroll
    for (int nt = 0; nt < 8; nt++) {
        int col = n0 + wn * 64 + nt * 8 + c0 * 2;
        float b0v = bias[col], b1v = bias[col + 1];
#pragma unroll
        for (int mt = 0; mt < 4; mt++) {
            int row = m0 + wm * 64 + mt * 16 + r0;
            uint2 v0 = make_uint2(f2tf(acc[mt][nt][0] + b0v), f2tf(acc[mt][nt][1] + b1v));
            uint2 v1 = make_uint2(f2tf(acc[mt][nt][2] + b0v), f2tf(acc[mt][nt][3] + b1v));
            *(uint2*)&C[(size_t)row * D3 + col] = v0;
            *(uint2*)&C[(size_t)(row + 8) * D3 + col] = v1;
        }
    }
}

// ------------------------- tensor-core attention (inputs already tf32-rounded) -------------------------
#define QSTR 68
#define KSTR 68
#define VSTR 72
#define PSTR 260

template<int S>
__global__ __launch_bounds__(256)
void attn_tc_kernel(const float* __restrict__ qkv,
                    long groupStride, long posStride,
                    const float* __restrict__ neg, long negGroupStride, long negStride,
                    float* __restrict__ outp, long outGroupStride, long outPosStride) {
    constexpr int HS = S / 2;
    constexpr int NT = HS / 8;
    extern __shared__ float smf[];
    float* Vs   = smf;                  // S x VSTR
    float* Qs   = Vs + S * VSTR;        // 64 x QSTR
    float* negs = Qs + 64 * QSTR;       // S
    float* pmax = negs + S;             // 2 x 64
    float* psum = pmax + 128;           // 2 x 64
    float* Ks   = psum + 128;           // max(S*KSTR, 64*PSTR)
    float* Ps   = Ks;                   // alias (Ks dead after QK)

    int h   = blockIdx.y;
    int grp = blockIdx.z;
    int i0  = blockIdx.x * 64;
    const float* base = qkv + (size_t)grp * groupStride;
    const float* qb = base + h * 64;
    const float* kb = base + 768 + h * 64;
    const float* vb = base + 1536 + h * 64;
    int tid = threadIdx.x;

    for (int idx = tid; idx < S * 16; idx += 256) {
        int j = idx >> 4, c4 = (idx & 15) << 2;
        float4 k4 = *(const float4*)(kb + (size_t)j * posStride + c4);
        float4 v4 = *(const float4*)(vb + (size_t)j * posStride + c4);
        float* kd = &Ks[j * KSTR + c4];
        kd[0] = k4.x; kd[1] = k4.y; kd[2] = k4.z; kd[3] = k4.w;
        float* vd = &Vs[j * VSTR + c4];
        vd[0] = v4.x; vd[1] = v4.y; vd[2] = v4.z; vd[3] = v4.w;
    }
    for (int idx = tid; idx < 64 * 16; idx += 256) {
        int i = idx >> 4, c4 = (idx & 15) << 2;
        float4 q4 = *(const float4*)(qb + (size_t)(i0 + i) * posStride + c4);
        float* qd = &Qs[i * QSTR + c4];
        qd[0] = q4.x * 0.125f; qd[1] = q4.y * 0.125f;    // exponent-only scale: stays tf32
        qd[2] = q4.z * 0.125f; qd[3] = q4.w * 0.125f;
    }
    if (tid < S) negs[tid] = neg[(size_t)grp * negGroupStride + (size_t)tid * negStride];
    __syncthreads();

    int w = tid >> 5, lane = tid & 31;
    int r0 = lane >> 2, c0 = lane & 3;
    int wr = w & 3;
    int sh = w >> 2;
    int colbase = sh * HS;
    int rowA = wr * 16 + r0;

    const uint32_t* Qu = (const uint32_t*)Qs;
    const uint32_t* Ku = (const uint32_t*)Ks;
    const uint32_t* Vu = (const uint32_t*)Vs;

    // ---- QK^T scores (no cvt: data already tf32) ----
    float acc[NT][4];
#pragma unroll
    for (int nt = 0; nt < NT; nt++)
#pragma unroll
        for (int q = 0; q < 4; q++) acc[nt][q] = 0.0f;

#pragma unroll
    for (int kc = 0; kc < 8; kc++) {
        int k0 = kc * 8;
        uint32_t a0 = Qu[rowA * QSTR + k0 + c0];
        uint32_t a1 = Qu[(rowA + 8) * QSTR + k0 + c0];
        uint32_t a2 = Qu[rowA * QSTR + k0 + c0 + 4];
        uint32_t a3 = Qu[(rowA + 8) * QSTR + k0 + c0 + 4];
#pragma unroll
        for (int nt = 0; nt < NT; nt++) {
            int j = colbase + nt * 8 + r0;
            uint32_t b0 = Ku[j * KSTR + k0 + c0];
            uint32_t b1 = Ku[j * KSTR + k0 + c0 + 4];
            mma8(acc[nt], a0, a1, a2, a3, b0, b1);
        }
    }

    // ---- mask + row max (local to this key-half) ----
    float mlo = -3.4e38f, mhi = -3.4e38f;
#pragma unroll
    for (int nt = 0; nt < NT; nt++) {
        int cA = colbase + nt * 8 + c0 * 2;
        float n0v = negs[cA], n1v = negs[cA + 1];
        acc[nt][0] += n0v; acc[nt][1] += n1v;
        acc[nt][2] += n0v; acc[nt][3] += n1v;
        mlo = fmaxf(mlo, fmaxf(acc[nt][0], acc[nt][1]));
        mhi = fmaxf(mhi, fmaxf(acc[nt][2], acc[nt][3]));
    }
#pragma unroll
    for (int o = 1; o <= 2; o <<= 1) {
        mlo = fmaxf(mlo, __shfl_xor_sync(0xffffffffu, mlo, o));
        mhi = fmaxf(mhi, __shfl_xor_sync(0xffffffffu, mhi, o));
    }
    if (c0 == 0) {
        pmax[sh * 64 + wr * 16 + r0] = mlo;
        pmax[sh * 64 + wr * 16 + r0 + 8] = mhi;
    }
    __syncthreads();

    // ---- global max, exp, local sum, write P ----
    float gmlo = fmaxf(pmax[wr * 16 + r0], pmax[64 + wr * 16 + r0]);
    float gmhi = fmaxf(pmax[wr * 16 + r0 + 8], pmax[64 + wr * 16 + r0 + 8]);
    float slo = 0.0f, shi2 = 0.0f;
#pragma unroll
    for (int nt = 0; nt < NT; nt++) {
        acc[nt][0] = __expf(acc[nt][0] - gmlo);
        acc[nt][1] = __expf(acc[nt][1] - gmlo);
        acc[nt][2] = __expf(acc[nt][2] - gmhi);
        acc[nt][3] = __expf(acc[nt][3] - gmhi);
        slo += acc[nt][0] + acc[nt][1];
        shi2 += acc[nt][2] + acc[nt][3];
    }
#pragma unroll
    for (int o = 1; o <= 2; o <<= 1) {
        slo += __shfl_xor_sync(0xffffffffu, slo, o);
        shi2 += __shfl_xor_sync(0xffffffffu, shi2, o);
    }
    if (c0 == 0) {
        psum[sh * 64 + wr * 16 + r0] = slo;
        psum[sh * 64 + wr * 16 + r0 + 8] = shi2;
    }
    // write P already tf32-rounded so PV loop needs no cvt
#pragma unroll
    for (int nt = 0; nt < NT; nt++) {
        int cA = colbase + nt * 8 + c0 * 2;
        *(uint2*)&Ps[(wr * 16 + r0) * PSTR + cA] =
            make_uint2(f2tf(acc[nt][0]), f2tf(acc[nt][1]));
        *(uint2*)&Ps[(wr * 16 + r0 + 8) * PSTR + cA] =
            make_uint2(f2tf(acc[nt][2]), f2tf(acc[nt][3]));
    }
    __syncthreads();

    // ---- PV: out[16 rows][32 dims] per warp, K = S ----
    const uint32_t* Pu = (const uint32_t*)Ps;
    float oacc[4][4];
#pragma unroll
    for (int nt = 0; nt < 4; nt++)
#pragma unroll
        for (int q = 0; q < 4; q++) oacc[nt][q] = 0.0f;

#pragma unroll 4
    for (int kc = 0; kc < S / 8; kc++) {
        int k0 = kc * 8;
        uint32_t a0 = Pu[rowA * PSTR + k0 + c0];
        uint32_t a1 = Pu[(rowA + 8) * PSTR + k0 + c0];
        uint32_t a2 = Pu[rowA * PSTR + k0 + c0 + 4];
        uint32_t a3 = Pu[(rowA + 8) * PSTR + k0 + c0 + 4];
#pragma unroll
        for (int nt = 0; nt < 4; nt++) {
            int d = sh * 32 + nt * 8 + r0;
            uint32_t b0 = Vu[(k0 + c0) * VSTR + d];
            uint32_t b1 = Vu[(k0 + c0 + 4) * VSTR + d];
            mma8(oacc[nt], a0, a1, a2, a3, b0, b1);
        }
    }

    // ---- epilogue: scale by 1/sum, store ----
    float rlo = 1.0f / (psum[wr * 16 + r0] + psum[64 + wr * 16 + r0]);
    float rhi = 1.0f / (psum[wr * 16 + r0 + 8] + psum[64 + wr * 16 + r0 + 8]);
#pragma unroll
    for (int nt = 0; nt < 4; nt++) {
        int d = sh * 32 + nt * 8 + c0 * 2;
        float* olo = outp + (size_t)grp * outGroupStride
                   + (size_t)(i0 + wr * 16 + r0) * outPosStride + h * 64 + d;
        float* ohi = outp + (size_t)grp * outGroupStride
                   + (size_t)(i0 + wr * 16 + r0 + 8) * outPosStride + h * 64 + d;
        *(float2*)olo = make_float2(oacc[nt][0] * rlo, oacc[nt][1] * rlo);
        *(float2*)ohi = make_float2(oacc[nt][2] * rhi, oacc[nt][3] * rhi);
    }
}

#define ATTN_SMEM(S) ((S * VSTR + 64 * QSTR + S + 256 + \
                      ((S * KSTR > 64 * PSTR) ? S * KSTR : 64 * PSTR)) * 4)

// ------------------------- residual + LayerNorm -------------------------
__global__ __launch_bounds__(256)
void ln_kernel(const float* __restrict__ x, const float* __restrict__ r,
               const float* __restrict__ g, const float* __restrict__ b,
               float* __restrict__ out) {
    __shared__ float rs[8], rq[8], sh[2];
    int row = blockIdx.x, tid = threadIdx.x;
    size_t b0 = (size_t)row * DD;
    float v[3]; float s = 0.0f, q = 0.0f;
#pragma unroll
    for (int u = 0; u < 3; u++) {
        int c = tid + u * 256;
        float t = x[b0 + c] + r[b0 + c];
        v[u] = t; s += t; q += t * t;
    }
#pragma unroll
    for (int o = 16; o > 0; o >>= 1) {
        s += __shfl_down_sync(0xffffffffu, s, o);
        q += __shfl_down_sync(0xffffffffu, q, o);
    }
    int wid = tid >> 5, lane = tid & 31;
    if (lane == 0) { rs[wid] = s; rq[wid] = q; }
    __syncthreads();
    if (tid == 0) {
        float S = 0.0f, Q = 0.0f;
#pragma unroll
        for (int w = 0; w < 8; w++) { S += rs[w]; Q += rq[w]; }
        float mu = S * (1.0f / 768.0f);
        sh[0] = mu;
        sh[1] = rsqrtf(Q * (1.0f / 768.0f) - mu * mu + 1e-5f);
    }
    __syncthreads();
    float mu = sh[0], inv = sh[1];
#pragma unroll
    for (int u = 0; u < 3; u++) {
        int c = tid + u * 256;
        out[b0 + c] = (v[u] - mu) * inv * g[c] + b[c];
    }
}

// ------------------------- launch -------------------------
extern "C" void kernel_launch(void* const* d_in, const int* in_sizes, int n_in,
                              void* d_out, int out_size) {
    const float* x     = (const float*)d_in[0];
    const float* w_row = (const float*)d_in[1];
    const float* b_row = (const float*)d_in[2];
    const float* w_col = (const float*)d_in[3];
    const float* b_col = (const float*)d_in[4];
    const float* g1    = (const float*)d_in[5];
    const float* be1   = (const float*)d_in[6];
    const float* g2    = (const float*)d_in[7];
    const float* be2   = (const float*)d_in[8];
    const void*  mask  = d_in[9];
    float* out = (float*)d_out;

    float *qkv, *tmp, *acv, *wcv, *neg;
    cudaGetSymbolAddress((void**)&qkv, g_qkv);
    cudaGetSymbolAddress((void**)&tmp, g_tmp);
    cudaGetSymbolAddress((void**)&acv, g_acv);
    cudaGetSymbolAddress((void**)&wcv, g_wcv);
    cudaGetSymbolAddress((void**)&neg, g_neg);

    cudaFuncSetAttribute(attn_tc_kernel<256>, cudaFuncAttributeMaxDynamicSharedMemorySize, ATTN_SMEM(256));
    cudaFuncSetAttribute(attn_tc_kernel<128>, cudaFuncAttributeMaxDynamicSharedMemorySize, ATTN_SMEM(128));
    cudaFuncSetAttribute(gemm_mma_kernel, cudaFuncAttributeMaxDynamicSharedMemorySize, GEMM_SMEM);

    neg_kernel<<<1, 256>>>(mask);

    dim3 ggrid(D3 / GN, NROWS / GM);   // (18, 256)
    const int ACV_BLKS = (int)(((size_t)NROWS * DD) / 1024);   // 24576
    const int WCV_BLKS = (int)(((size_t)D3 * DD) / 1024);      // 1728

    // ---- row attention block ----
    cvt_tf32_kernel<<<ACV_BLKS, 256>>>(x, acv);
    cvt_tf32_kernel<<<WCV_BLKS, 256>>>(w_row, wcv);
    gemm_mma_kernel<<<ggrid, 128, GEMM_SMEM>>>(acv, wcv, b_row, qkv);
    {
        dim3 agrid(LL / 64, 12, EE);
        attn_tc_kernel<256><<<agrid, 256, ATTN_SMEM(256)>>>(
            qkv, (long)LL * D3, (long)D3,
            neg, (long)LL, 1L,
            tmp, (long)LL * DD, (long)DD);
    }
    ln_kernel<<<NROWS, 256>>>(x, tmp, g1, be1, out);

    // ---- column attention block ----
    cvt_tf32_kernel<<<ACV_BLKS, 256>>>(out, acv);
    cvt_tf32_kernel<<<WCV_BLKS, 256>>>(w_col, wcv);
    gemm_mma_kernel<<<ggrid, 128, GEMM_SMEM>>>(acv, wcv, b_col, qkv);
    {
        dim3 agrid(EE / 64, 12, LL);
        attn_tc_kernel<128><<<agrid, 256, ATTN_SMEM(128)>>>(
            qkv, (long)D3, (long)LL * D3,
            neg, 1L, (long)LL,
            tmp, (long)DD, (long)LL * DD);
    }
    ln_kernel<<<NROWS, 256>>>(out, tmp, g2, be2, out);
}

// round 8
// speedup vs baseline: 2.7635x; 1.0944x over previous
#include <cuda_runtime.h>
#include <cuda_bf16.h>
#include <stdint.h>
#include <math.h>

// Problem constants: B=1, E=128, L=256, D=768, H=12, DH=64
#define EE 128
#define LL 256
#define DD 768
#define D3 2304
#define NROWS 32768          // E*L
#define NEGV (-10000.0f)

typedef unsigned long long ull;

// ------------------------- scratch (static device globals; no runtime alloc) -------------------------
__device__ float g_qkv[(size_t)NROWS * D3];   // 302 MB (tf32-rounded by GEMM epilogue)
__device__ float g_tmp[(size_t)NROWS * DD];   // 100 MB
__device__ float g_acv[(size_t)NROWS * DD];   // 100 MB (tf32-rounded activations)
__device__ float g_wcv[(size_t)D3 * DD];      // 7 MB  (tf32-rounded weights)
__device__ float g_neg[NROWS];

// ------------------------- PTX helpers -------------------------
__device__ __forceinline__ uint32_t smem_u32(const void* p) {
    uint32_t a;
    asm("{ .reg .u64 t; cvta.to.shared.u64 t, %1; cvt.u32.u64 %0, t; }" : "=r"(a) : "l"(p));
    return a;
}
__device__ __forceinline__ void cp_async16(uint32_t dst, const void* src) {
    asm volatile("cp.async.cg.shared.global [%0], [%1], 16;" :: "r"(dst), "l"(src) : "memory");
}
__device__ __forceinline__ uint32_t f2tf(float f) {
    uint32_t r; asm("cvt.rna.tf32.f32 %0, %1;" : "=r"(r) : "f"(f)); return r;
}
__device__ __forceinline__ void mma8(float* c, uint32_t a0, uint32_t a1, uint32_t a2, uint32_t a3,
                                     uint32_t b0, uint32_t b1) {
    asm volatile(
        "mma.sync.aligned.m16n8k8.row.col.f32.tf32.tf32.f32 "
        "{%0,%1,%2,%3}, {%4,%5,%6,%7}, {%8,%9}, {%0,%1,%2,%3};"
        : "+f"(c[0]), "+f"(c[1]), "+f"(c[2]), "+f"(c[3])
        : "r"(a0), "r"(a1), "r"(a2), "r"(a3), "r"(b0), "r"(b1));
}

// ------------------------- padding mask -> additive neg, with dtype auto-detect -------------------------
__global__ void neg_kernel(const void* mraw) {
    __shared__ int notInt, notFloat;
    int tid = threadIdx.x;
    if (tid == 0) { notInt = 0; notFloat = 0; }
    __syncthreads();
    const unsigned int* w = (const unsigned int*)mraw;
    int badI = 0, badF = 0;
    for (int i = tid; i < 8192; i += 256) {
        unsigned int v = w[i];
        if (v > 1u) badI = 1;
        if (v != 0u && v != 0x3F800000u) badF = 1;
    }
    if (badI) notInt = 1;
    if (badF) notFloat = 1;
    __syncthreads();
    int mode = (!notInt) ? 0 : ((!notFloat) ? 1 : 2);  // 0=int32, 1=float32, 2=uint8
    for (int i = tid; i < NROWS; i += 256) {
        bool m;
        if (mode == 0)      m = ((const int*)mraw)[i] != 0;
        else if (mode == 1) m = ((const float*)mraw)[i] != 0.0f;
        else                m = ((const unsigned char*)mraw)[i] != 0;
        g_neg[i] = m ? NEGV : 0.0f;
    }
}

// ------------------------- fp32 -> tf32 (rna) pre-pass -------------------------
__global__ __launch_bounds__(256)
void cvt_tf32_kernel(const float* __restrict__ in, float* __restrict__ out) {
    size_t i = ((size_t)blockIdx.x * 256 + threadIdx.x) * 4;
    float4 v = *(const float4*)(in + i);
    *(uint4*)(out + i) = make_uint4(f2tf(v.x), f2tf(v.y), f2tf(v.z), f2tf(v.w));
}

// ------------------------- tf32 mma.sync GEMM (unchanged from R7) -------------------------
#define GM 128
#define GN 128
#define KB 32
#define NST 24                       // 768/32
#define ASTR 36
#define AFLOATS (128 * ASTR)
#define BFLOATS (128 * ASTR)
#define STAGEF (AFLOATS + BFLOATS)
#define GEMM_SMEM (3 * STAGEF * 4)   // 110592 bytes

__device__ __forceinline__ void load_stage(float* sm, int stg, const float* Ab, const float* Wb,
                                           int k0, int tid) {
    float* As = sm + stg * STAGEF;
    float* Bs = As + AFLOATS;
    uint32_t as_u = smem_u32(As), bs_u = smem_u32(Bs);
#pragma unroll
    for (int i = 0; i < 8; i++) {
        int idx = tid + i * 128;
        int row = idx >> 3, ch = idx & 7;
        cp_async16(as_u + row * (ASTR * 4) + ch * 16, Ab + (size_t)row * DD + k0 + ch * 4);
    }
#pragma unroll
    for (int i = 0; i < 8; i++) {
        int idx = tid + i * 128;
        int row = idx >> 3, ch = idx & 7;
        cp_async16(bs_u + row * (ASTR * 4) + ch * 16, Wb + (size_t)row * DD + k0 + ch * 4);
    }
}

__global__ __launch_bounds__(128, 2)
void gemm_mma_kernel(const float* __restrict__ A, const float* __restrict__ W,
                     const float* __restrict__ bias, float* __restrict__ C) {
    extern __shared__ float sm[];
    int tid = threadIdx.x, lane = tid & 31, w = tid >> 5;
    int wm = w & 1, wn = w >> 1;
    int m0 = blockIdx.y * GM, n0 = blockIdx.x * GN;
    const float* Ab = A + (size_t)m0 * DD;
    const float* Wb = W + (size_t)n0 * DD;
    int r0 = lane >> 2, c0 = lane & 3;

    float acc[4][8][4];
#pragma unroll
    for (int mt = 0; mt < 4; mt++)
#pragma unroll
        for (int nt = 0; nt < 8; nt++)
#pragma unroll
            for (int q = 0; q < 4; q++) acc[mt][nt][q] = 0.0f;

    load_stage(sm, 0, Ab, Wb, 0, tid);
    asm volatile("cp.async.commit_group;" ::: "memory");
    load_stage(sm, 1, Ab, Wb, KB, tid);
    asm volatile("cp.async.commit_group;" ::: "memory");

    for (int s = 0; s < NST; ++s) {
        int b = s % 3;
        asm volatile("cp.async.wait_group 1;" ::: "memory");
        __syncthreads();
        if (s + 2 < NST) load_stage(sm, (s + 2) % 3, Ab, Wb, (s + 2) * KB, tid);
        asm volatile("cp.async.commit_group;" ::: "memory");

        const uint32_t* As = (const uint32_t*)(sm + b * STAGEF);
        const uint32_t* Bs = As + AFLOATS;
#pragma unroll
        for (int ks = 0; ks < 4; ks++) {
            int K0 = ks * 8 + c0;
            uint32_t bf[8][2];
#pragma unroll
            for (int nt = 0; nt < 8; nt++) {
                int N0 = wn * 64 + nt * 8 + r0;
                bf[nt][0] = Bs[N0 * ASTR + K0];
                bf[nt][1] = Bs[N0 * ASTR + K0 + 4];
            }
#pragma unroll
            for (int mt = 0; mt < 4; mt++) {
                int R = wm * 64 + mt * 16 + r0;
                uint32_t a0 = As[R * ASTR + K0];
                uint32_t a1 = As[(R + 8) * ASTR + K0];
                uint32_t a2 = As[R * ASTR + K0 + 4];
                uint32_t a3 = As[(R + 8) * ASTR + K0 + 4];
#pragma unroll
                for (int nt = 0; nt < 8; nt++)
                    mma8(acc[mt][nt], a0, a1, a2, a3, bf[nt][0], bf[nt][1]);
            }
        }
    }
    asm volatile("cp.async.wait_group 0;" ::: "memory");

#pragma unroll
    for (int nt = 0; nt < 8; nt++) {
        int col = n0 + wn * 64 + nt * 8 + c0 * 2;
        float b0v = bias[col], b1v = bias[col + 1];
#pragma unroll
        for (int mt = 0; mt < 4; mt++) {
            int row = m0 + wm * 64 + mt * 16 + r0;
            uint2 v0 = make_uint2(f2tf(acc[mt][nt][0] + b0v), f2tf(acc[mt][nt][1] + b1v));
            uint2 v1 = make_uint2(f2tf(acc[mt][nt][2] + b0v), f2tf(acc[mt][nt][3] + b1v));
            *(uint2*)&C[(size_t)row * D3 + col] = v0;
            *(uint2*)&C[(size_t)(row + 8) * D3 + col] = v1;
        }
    }
}

// ------------------------- tensor-core attention (QK: 64-row x S/8-col strips) -------------------------
#define QSTR 68
#define KSTR 68
#define VSTR 72

template<int S>
__global__ __launch_bounds__(256, (S == 128) ? 2 : 1)
void attn_tc_kernel(const float* __restrict__ qkv,
                    long groupStride, long posStride,
                    const float* __restrict__ neg, long negGroupStride, long negStride,
                    float* __restrict__ outp, long outGroupStride, long outPosStride) {
    constexpr int PSTR = S + 4;
    constexpr int CW = S / 8;       // column strip per warp in QK
    constexpr int NTQ = CW / 8;     // 4 (S=256) / 2 (S=128)
    extern __shared__ float smf[];
    float* Vs   = smf;                   // S x VSTR
    float* Qs   = Vs + S * VSTR;         // 64 x QSTR
    float* negs = Qs + 64 * QSTR;        // S
    float* pmax = negs + S;              // 8 x 64
    float* psum = pmax + 512;            // 8 x 64
    float* Ks   = psum + 512;            // max(S*KSTR, 64*PSTR)
    float* Ps   = Ks;                    // alias (Ks dead after QK)

    int h   = blockIdx.y;
    int grp = blockIdx.z;
    int i0  = blockIdx.x * 64;
    const float* base = qkv + (size_t)grp * groupStride;
    const float* qb = base + h * 64;
    const float* kb = base + 768 + h * 64;
    const float* vb = base + 1536 + h * 64;
    int tid = threadIdx.x;

    for (int idx = tid; idx < S * 16; idx += 256) {
        int j = idx >> 4, c4 = (idx & 15) << 2;
        float4 k4 = *(const float4*)(kb + (size_t)j * posStride + c4);
        float4 v4 = *(const float4*)(vb + (size_t)j * posStride + c4);
        float* kd = &Ks[j * KSTR + c4];
        kd[0] = k4.x; kd[1] = k4.y; kd[2] = k4.z; kd[3] = k4.w;
        float* vd = &Vs[j * VSTR + c4];
        vd[0] = v4.x; vd[1] = v4.y; vd[2] = v4.z; vd[3] = v4.w;
    }
    for (int idx = tid; idx < 64 * 16; idx += 256) {
        int i = idx >> 4, c4 = (idx & 15) << 2;
        float4 q4 = *(const float4*)(qb + (size_t)(i0 + i) * posStride + c4);
        float* qd = &Qs[i * QSTR + c4];
        qd[0] = q4.x * 0.125f; qd[1] = q4.y * 0.125f;    // exponent-only scale: stays tf32
        qd[2] = q4.z * 0.125f; qd[3] = q4.w * 0.125f;
    }
    if (tid < S) negs[tid] = neg[(size_t)grp * negGroupStride + (size_t)tid * negStride];
    __syncthreads();

    int w = tid >> 5, lane = tid & 31;
    int r0 = lane >> 2, c0 = lane & 3;
    int colb = w * CW;

    const uint32_t* Qu = (const uint32_t*)Qs;
    const uint32_t* Ku = (const uint32_t*)Ks;
    const uint32_t* Vu = (const uint32_t*)Vs;

    // ---- QK^T: all 64 rows x CW-col strip per warp ----
    float acc[4][NTQ][4];
#pragma unroll
    for (int mt = 0; mt < 4; mt++)
#pragma unroll
        for (int nt = 0; nt < NTQ; nt++)
#pragma unroll
            for (int q = 0; q < 4; q++) acc[mt][nt][q] = 0.0f;

#pragma unroll
    for (int kc = 0; kc < 8; kc++) {
        int k0 = kc * 8;
        uint32_t bfr[NTQ][2];
#pragma unroll
        for (int nt = 0; nt < NTQ; nt++) {
            int j = colb + nt * 8 + r0;
            bfr[nt][0] = Ku[j * KSTR + k0 + c0];
            bfr[nt][1] = Ku[j * KSTR + k0 + c0 + 4];
        }
#pragma unroll
        for (int mt = 0; mt < 4; mt++) {
            int R = mt * 16 + r0;
            uint32_t a0 = Qu[R * QSTR + k0 + c0];
            uint32_t a1 = Qu[(R + 8) * QSTR + k0 + c0];
            uint32_t a2 = Qu[R * QSTR + k0 + c0 + 4];
            uint32_t a3 = Qu[(R + 8) * QSTR + k0 + c0 + 4];
#pragma unroll
            for (int nt = 0; nt < NTQ; nt++)
                mma8(acc[mt][nt], a0, a1, a2, a3, bfr[nt][0], bfr[nt][1]);
        }
    }

    // ---- mask + per-warp partial row max ----
    float mlo[4], mhi[4];
#pragma unroll
    for (int mt = 0; mt < 4; mt++) { mlo[mt] = -3.4e38f; mhi[mt] = -3.4e38f; }
#pragma unroll
    for (int nt = 0; nt < NTQ; nt++) {
        int cA = colb + nt * 8 + c0 * 2;
        float n0v = negs[cA], n1v = negs[cA + 1];
#pragma unroll
        for (int mt = 0; mt < 4; mt++) {
            acc[mt][nt][0] += n0v; acc[mt][nt][1] += n1v;
            acc[mt][nt][2] += n0v; acc[mt][nt][3] += n1v;
            mlo[mt] = fmaxf(mlo[mt], fmaxf(acc[mt][nt][0], acc[mt][nt][1]));
            mhi[mt] = fmaxf(mhi[mt], fmaxf(acc[mt][nt][2], acc[mt][nt][3]));
        }
    }
#pragma unroll
    for (int mt = 0; mt < 4; mt++) {
#pragma unroll
        for (int o = 1; o <= 2; o <<= 1) {
            mlo[mt] = fmaxf(mlo[mt], __shfl_xor_sync(0xffffffffu, mlo[mt], o));
            mhi[mt] = fmaxf(mhi[mt], __shfl_xor_sync(0xffffffffu, mhi[mt], o));
        }
        if (c0 == 0) {
            pmax[w * 64 + mt * 16 + r0] = mlo[mt];
            pmax[w * 64 + mt * 16 + r0 + 8] = mhi[mt];
        }
    }
    __syncthreads();     // pmax ready; also: all warps done reading Ks

    // ---- global max, exp, partial sums, write P (tf32) ----
#pragma unroll
    for (int mt = 0; mt < 4; mt++) {
        int R = mt * 16 + r0;
        float gmlo = pmax[R], gmhi = pmax[R + 8];
#pragma unroll
        for (int ww = 1; ww < 8; ww++) {
            gmlo = fmaxf(gmlo, pmax[ww * 64 + R]);
            gmhi = fmaxf(gmhi, pmax[ww * 64 + R + 8]);
        }
        float slo = 0.0f, shi = 0.0f;
#pragma unroll
        for (int nt = 0; nt < NTQ; nt++) {
            acc[mt][nt][0] = __expf(acc[mt][nt][0] - gmlo);
            acc[mt][nt][1] = __expf(acc[mt][nt][1] - gmlo);
            acc[mt][nt][2] = __expf(acc[mt][nt][2] - gmhi);
            acc[mt][nt][3] = __expf(acc[mt][nt][3] - gmhi);
            slo += acc[mt][nt][0] + acc[mt][nt][1];
            shi += acc[mt][nt][2] + acc[mt][nt][3];
        }
#pragma unroll
        for (int o = 1; o <= 2; o <<= 1) {
            slo += __shfl_xor_sync(0xffffffffu, slo, o);
            shi += __shfl_xor_sync(0xffffffffu, shi, o);
        }
        if (c0 == 0) {
            psum[w * 64 + R] = slo;
            psum[w * 64 + R + 8] = shi;
        }
#pragma unroll
        for (int nt = 0; nt < NTQ; nt++) {
            int cA = colb + nt * 8 + c0 * 2;
            *(uint2*)&Ps[R * PSTR + cA] =
                make_uint2(f2tf(acc[mt][nt][0]), f2tf(acc[mt][nt][1]));
            *(uint2*)&Ps[(R + 8) * PSTR + cA] =
                make_uint2(f2tf(acc[mt][nt][2]), f2tf(acc[mt][nt][3]));
        }
    }
    __syncthreads();

    // ---- PV: warp = (row-quarter wr, dim-half sh), out 16x32, K = S ----
    int wr = w & 3, sh = w >> 2;
    int rowA = wr * 16 + r0;
    const uint32_t* Pu = (const uint32_t*)Ps;
    float oacc[4][4];
#pragma unroll
    for (int nt = 0; nt < 4; nt++)
#pragma unroll
        for (int q = 0; q < 4; q++) oacc[nt][q] = 0.0f;

#pragma unroll 4
    for (int kc = 0; kc < S / 8; kc++) {
        int k0 = kc * 8;
        uint32_t a0 = Pu[rowA * PSTR + k0 + c0];
        uint32_t a1 = Pu[(rowA + 8) * PSTR + k0 + c0];
        uint32_t a2 = Pu[rowA * PSTR + k0 + c0 + 4];
        uint32_t a3 = Pu[(rowA + 8) * PSTR + k0 + c0 + 4];
#pragma unroll
        for (int nt = 0; nt < 4; nt++) {
            int d = sh * 32 + nt * 8 + r0;
            uint32_t b0 = Vu[(k0 + c0) * VSTR + d];
            uint32_t b1 = Vu[(k0 + c0 + 4) * VSTR + d];
            mma8(oacc[nt], a0, a1, a2, a3, b0, b1);
        }
    }

    // ---- epilogue: 1/sum scale, store ----
    float slo = psum[rowA], shi = psum[rowA + 8];
#pragma unroll
    for (int ww = 1; ww < 8; ww++) {
        slo += psum[ww * 64 + rowA];
        shi += psum[ww * 64 + rowA + 8];
    }
    float rlo = 1.0f / slo, rhi = 1.0f / shi;
#pragma unroll
    for (int nt = 0; nt < 4; nt++) {
        int d = sh * 32 + nt * 8 + c0 * 2;
        float* olo = outp + (size_t)grp * outGroupStride
                   + (size_t)(i0 + rowA) * outPosStride + h * 64 + d;
        float* ohi = outp + (size_t)grp * outGroupStride
                   + (size_t)(i0 + rowA + 8) * outPosStride + h * 64 + d;
        *(float2*)olo = make_float2(oacc[nt][0] * rlo, oacc[nt][1] * rlo);
        *(float2*)ohi = make_float2(oacc[nt][2] * rhi, oacc[nt][3] * rhi);
    }
}

#define ATTN_SMEM(S) ((S * VSTR + 64 * QSTR + S + 1024 + \
                      ((S * KSTR > 64 * (S + 4)) ? S * KSTR : 64 * (S + 4))) * 4)

// ------------------------- residual + LayerNorm (optional tf32 second output) -------------------------
__global__ __launch_bounds__(256)
void ln_kernel(const float* __restrict__ x, const float* __restrict__ r,
               const float* __restrict__ g, const float* __restrict__ b,
               float* __restrict__ out, float* __restrict__ cvtout) {
    __shared__ float rs[8], rq[8], sh[2];
    int row = blockIdx.x, tid = threadIdx.x;
    size_t b0 = (size_t)row * DD;
    float v[3]; float s = 0.0f, q = 0.0f;
#pragma unroll
    for (int u = 0; u < 3; u++) {
        int c = tid + u * 256;
        float t = x[b0 + c] + r[b0 + c];
        v[u] = t; s += t; q += t * t;
    }
#pragma unroll
    for (int o = 16; o > 0; o >>= 1) {
        s += __shfl_down_sync(0xffffffffu, s, o);
        q += __shfl_down_sync(0xffffffffu, q, o);
    }
    int wid = tid >> 5, lane = tid & 31;
    if (lane == 0) { rs[wid] = s; rq[wid] = q; }
    __syncthreads();
    if (tid == 0) {
        float S = 0.0f, Q = 0.0f;
#pragma unroll
        for (int w = 0; w < 8; w++) { S += rs[w]; Q += rq[w]; }
        float mu = S * (1.0f / 768.0f);
        sh[0] = mu;
        sh[1] = rsqrtf(Q * (1.0f / 768.0f) - mu * mu + 1e-5f);
    }
    __syncthreads();
    float mu = sh[0], inv = sh[1];
#pragma unroll
    for (int u = 0; u < 3; u++) {
        int c = tid + u * 256;
        float o = (v[u] - mu) * inv * g[c] + b[c];
        out[b0 + c] = o;
        if (cvtout) *(uint32_t*)&cvtout[b0 + c] = f2tf(o);
    }
}

// ------------------------- launch -------------------------
extern "C" void kernel_launch(void* const* d_in, const int* in_sizes, int n_in,
                              void* d_out, int out_size) {
    const float* x     = (const float*)d_in[0];
    const float* w_row = (const float*)d_in[1];
    const float* b_row = (const float*)d_in[2];
    const float* w_col = (const float*)d_in[3];
    const float* b_col = (const float*)d_in[4];
    const float* g1    = (const float*)d_in[5];
    const float* be1   = (const float*)d_in[6];
    const float* g2    = (const float*)d_in[7];
    const float* be2   = (const float*)d_in[8];
    const void*  mask  = d_in[9];
    float* out = (float*)d_out;

    float *qkv, *tmp, *acv, *wcv, *neg;
    cudaGetSymbolAddress((void**)&qkv, g_qkv);
    cudaGetSymbolAddress((void**)&tmp, g_tmp);
    cudaGetSymbolAddress((void**)&acv, g_acv);
    cudaGetSymbolAddress((void**)&wcv, g_wcv);
    cudaGetSymbolAddress((void**)&neg, g_neg);

    cudaFuncSetAttribute(attn_tc_kernel<256>, cudaFuncAttributeMaxDynamicSharedMemorySize, ATTN_SMEM(256));
    cudaFuncSetAttribute(attn_tc_kernel<128>, cudaFuncAttributeMaxDynamicSharedMemorySize, ATTN_SMEM(128));
    cudaFuncSetAttribute(gemm_mma_kernel, cudaFuncAttributeMaxDynamicSharedMemorySize, GEMM_SMEM);

    neg_kernel<<<1, 256>>>(mask);

    dim3 ggrid(D3 / GN, NROWS / GM);   // (18, 256)
    const int ACV_BLKS = (int)(((size_t)NROWS * DD) / 1024);   // 24576
    const int WCV_BLKS = (int)(((size_t)D3 * DD) / 1024);      // 1728

    // ---- row attention block ----
    cvt_tf32_kernel<<<ACV_BLKS, 256>>>(x, acv);
    cvt_tf32_kernel<<<WCV_BLKS, 256>>>(w_row, wcv);
    gemm_mma_kernel<<<ggrid, 128, GEMM_SMEM>>>(acv, wcv, b_row, qkv);
    {
        dim3 agrid(LL / 64, 12, EE);
        attn_tc_kernel<256><<<agrid, 256, ATTN_SMEM(256)>>>(
            qkv, (long)LL * D3, (long)D3,
            neg, (long)LL, 1L,
            tmp, (long)LL * DD, (long)DD);
    }
    ln_kernel<<<NROWS, 256>>>(x, tmp, g1, be1, out, acv);   // dual-write: fp32 + tf32

    // ---- column attention block ----
    cvt_tf32_kernel<<<WCV_BLKS, 256>>>(w_col, wcv);
    gemm_mma_kernel<<<ggrid, 128, GEMM_SMEM>>>(acv, wcv, b_col, qkv);
    {
        dim3 agrid(EE / 64, 12, LL);
        attn_tc_kernel<128><<<agrid, 256, ATTN_SMEM(128)>>>(
            qkv, (long)D3, (long)LL * D3,
            neg, 1L, (long)LL,
            tmp, (long)DD, (long)LL * DD);
    }
    ln_kernel<<<NROWS, 256>>>(out, tmp, g2, be2, out, (float*)0);
}